// round 1
// baseline (speedup 1.0000x reference)
#include <cuda_runtime.h>
#include <math.h>

// Problem constants
#define BATCH   4
#define SEQ     2048
#define DM      2048            // d_model
#define NH      16
#define DH      128
#define MROWS   (BATCH * SEQ)   // 8192
#define QKV_N   (3 * DM)        // 6144

// Scratch (device globals: allocation-free per harness rules)
__device__ float g_qkv[(size_t)MROWS * QKV_N];   // [B*S, 3*DM]
__device__ float g_attn[(size_t)MROWS * DM];     // [B*S, DM] attention output

// ---------------------------------------------------------------------------
// GEMM + bias: C[M,N] = A[M,K] @ B[K,N] + bias[N]
// Tiles: BM=BN=128, BK=16, 256 threads, 8x8 per thread.
// ---------------------------------------------------------------------------
__global__ __launch_bounds__(256, 2) void gemm_bias_kernel(
    const float* __restrict__ A, const float* __restrict__ B,
    const float* __restrict__ bias, float* __restrict__ C,
    int M, int N, int K)
{
    __shared__ float As[16][132];   // transposed A tile, padded
    __shared__ float Bs[16][132];   // B tile, padded

    const int tid = threadIdx.x;
    const int tx = tid & 15;
    const int ty = tid >> 4;
    const int m0 = ty * 8;
    const int n0 = tx * 8;
    const int bm = blockIdx.y * 128;
    const int bn = blockIdx.x * 128;

    const int arow = tid >> 2;           // 0..63
    const int acol = (tid & 3) << 2;     // 0,4,8,12
    const int brow = tid >> 5;           // 0..7
    const int bcol = (tid & 31) << 2;    // 0..124

    float acc[8][8];
#pragma unroll
    for (int i = 0; i < 8; i++)
#pragma unroll
        for (int j = 0; j < 8; j++) acc[i][j] = 0.0f;

    for (int k0 = 0; k0 < K; k0 += 16) {
#pragma unroll
        for (int i = 0; i < 2; i++) {
            int r = arow + i * 64;
            float4 v = *reinterpret_cast<const float4*>(
                &A[(size_t)(bm + r) * K + k0 + acol]);
            As[acol + 0][r] = v.x;
            As[acol + 1][r] = v.y;
            As[acol + 2][r] = v.z;
            As[acol + 3][r] = v.w;
        }
#pragma unroll
        for (int i = 0; i < 2; i++) {
            int r = brow + i * 8;
            *reinterpret_cast<float4*>(&Bs[r][bcol]) =
                *reinterpret_cast<const float4*>(
                    &B[(size_t)(k0 + r) * N + bn + bcol]);
        }
        __syncthreads();

#pragma unroll
        for (int kk = 0; kk < 16; kk++) {
            float a[8], b[8];
            *reinterpret_cast<float4*>(&a[0]) = *reinterpret_cast<float4*>(&As[kk][m0]);
            *reinterpret_cast<float4*>(&a[4]) = *reinterpret_cast<float4*>(&As[kk][m0 + 4]);
            *reinterpret_cast<float4*>(&b[0]) = *reinterpret_cast<float4*>(&Bs[kk][n0]);
            *reinterpret_cast<float4*>(&b[4]) = *reinterpret_cast<float4*>(&Bs[kk][n0 + 4]);
#pragma unroll
            for (int i = 0; i < 8; i++)
#pragma unroll
                for (int j = 0; j < 8; j++)
                    acc[i][j] = fmaf(a[i], b[j], acc[i][j]);
        }
        __syncthreads();
    }

    float bv[8];
#pragma unroll
    for (int j = 0; j < 8; j++) bv[j] = bias[bn + n0 + j];

#pragma unroll
    for (int i = 0; i < 8; i++) {
        size_t row = (size_t)(bm + m0 + i);
        float4 o0, o1;
        o0.x = acc[i][0] + bv[0]; o0.y = acc[i][1] + bv[1];
        o0.z = acc[i][2] + bv[2]; o0.w = acc[i][3] + bv[3];
        o1.x = acc[i][4] + bv[4]; o1.y = acc[i][5] + bv[5];
        o1.z = acc[i][6] + bv[6]; o1.w = acc[i][7] + bv[7];
        *reinterpret_cast<float4*>(&C[row * N + bn + n0])     = o0;
        *reinterpret_cast<float4*>(&C[row * N + bn + n0 + 4]) = o1;
    }
}

// ---------------------------------------------------------------------------
// Flash attention (fp32, causal, online softmax).
// One CTA = one (b, h, 64-query tile). 256 threads as 16x16.
// Each thread: 4 query rows x (4 score cols | 8 output cols).
// smem: Q[64][132], K[64][132], V[64][132], P[64][68] = 118784 B dynamic.
// ---------------------------------------------------------------------------
#define LDK 132
#define LDP 68
#define ATTN_SMEM_BYTES ((3 * 64 * LDK + 64 * LDP) * (int)sizeof(float))

__global__ __launch_bounds__(256, 1) void attn_kernel(
    const float* __restrict__ qkv, float* __restrict__ attn_out)
{
    extern __shared__ float sm[];
    float* Qs = sm;
    float* Ks = Qs + 64 * LDK;
    float* Vs = Ks + 64 * LDK;
    float* Ps = Vs + 64 * LDK;

    const int qt = blockIdx.x;   // 0..31 query tile
    const int h  = blockIdx.y;   // 0..15
    const int b  = blockIdx.z;   // 0..3

    const int tid = threadIdx.x;
    const int tx = tid & 15;
    const int ty = tid >> 4;
    const int r0  = ty * 4;      // query rows (4)
    const int c0s = tx * 4;      // score cols (4)
    const int c0v = tx * 8;      // output cols (8)

    const float scale = 0.08838834764831845f;  // 1/sqrt(128)

    const float* qbase = qkv + (size_t)b * SEQ * QKV_N + h * DH;          // which=0
    const float* kbase = qbase + DM;                                      // which=1
    const float* vbase = qbase + 2 * DM;                                  // which=2

    // Load Q tile: 64 rows x 128 floats, 8 passes of 8 rows
    const int lrow = tid >> 5;            // 0..7
    const int lcol = (tid & 31) << 2;     // 0..124
#pragma unroll
    for (int p = 0; p < 8; p++) {
        int r = lrow + p * 8;
        *reinterpret_cast<float4*>(&Qs[r * LDK + lcol]) =
            *reinterpret_cast<const float4*>(
                &qbase[(size_t)(qt * 64 + r) * QKV_N + lcol]);
    }

    float m_r[4], l_r[4], o[4][8];
#pragma unroll
    for (int i = 0; i < 4; i++) {
        m_r[i] = -INFINITY;
        l_r[i] = 0.0f;
#pragma unroll
        for (int j = 0; j < 8; j++) o[i][j] = 0.0f;
    }

    for (int j = 0; j <= qt; j++) {
        __syncthreads();  // previous-iter P@V reads of Vs complete; Q visible on iter 0
#pragma unroll
        for (int p = 0; p < 8; p++) {
            int r = lrow + p * 8;
            size_t grow = (size_t)(j * 64 + r) * QKV_N + lcol;
            *reinterpret_cast<float4*>(&Ks[r * LDK + lcol]) =
                *reinterpret_cast<const float4*>(&kbase[grow]);
            *reinterpret_cast<float4*>(&Vs[r * LDK + lcol]) =
                *reinterpret_cast<const float4*>(&vbase[grow]);
        }
        __syncthreads();

        // Scores: s[4][4] = Q[r0..r0+3] . K[c0s..c0s+3]
        float s[4][4];
#pragma unroll
        for (int i = 0; i < 4; i++)
#pragma unroll
            for (int jj = 0; jj < 4; jj++) s[i][jj] = 0.0f;

#pragma unroll 4
        for (int d = 0; d < DH; d += 4) {
            float4 q0 = *reinterpret_cast<float4*>(&Qs[(r0 + 0) * LDK + d]);
            float4 q1 = *reinterpret_cast<float4*>(&Qs[(r0 + 1) * LDK + d]);
            float4 q2 = *reinterpret_cast<float4*>(&Qs[(r0 + 2) * LDK + d]);
            float4 q3 = *reinterpret_cast<float4*>(&Qs[(r0 + 3) * LDK + d]);
            float4 k0 = *reinterpret_cast<float4*>(&Ks[(c0s + 0) * LDK + d]);
            float4 k1 = *reinterpret_cast<float4*>(&Ks[(c0s + 1) * LDK + d]);
            float4 k2 = *reinterpret_cast<float4*>(&Ks[(c0s + 2) * LDK + d]);
            float4 k3 = *reinterpret_cast<float4*>(&Ks[(c0s + 3) * LDK + d]);
            float4 qv[4] = {q0, q1, q2, q3};
            float4 kv[4] = {k0, k1, k2, k3};
#pragma unroll
            for (int i = 0; i < 4; i++)
#pragma unroll
                for (int jj = 0; jj < 4; jj++) {
                    s[i][jj] = fmaf(qv[i].x, kv[jj].x, s[i][jj]);
                    s[i][jj] = fmaf(qv[i].y, kv[jj].y, s[i][jj]);
                    s[i][jj] = fmaf(qv[i].z, kv[jj].z, s[i][jj]);
                    s[i][jj] = fmaf(qv[i].w, kv[jj].w, s[i][jj]);
                }
        }

        // Scale + causal mask (only diagonal tile needs it)
#pragma unroll
        for (int i = 0; i < 4; i++)
#pragma unroll
            for (int jj = 0; jj < 4; jj++) {
                s[i][jj] *= scale;
                if (j == qt && (c0s + jj) > (r0 + i)) s[i][jj] = -1e30f;
            }

        // Online softmax per row (16 tx threads share each row group)
#pragma unroll
        for (int i = 0; i < 4; i++) {
            float mt = fmaxf(fmaxf(s[i][0], s[i][1]), fmaxf(s[i][2], s[i][3]));
            mt = fmaxf(mt, __shfl_xor_sync(0xffffffffu, mt, 1));
            mt = fmaxf(mt, __shfl_xor_sync(0xffffffffu, mt, 2));
            mt = fmaxf(mt, __shfl_xor_sync(0xffffffffu, mt, 4));
            mt = fmaxf(mt, __shfl_xor_sync(0xffffffffu, mt, 8));

            float mnew  = fmaxf(m_r[i], mt);
            float alpha = __expf(m_r[i] - mnew);
            m_r[i] = mnew;

            float p0 = __expf(s[i][0] - mnew);
            float p1 = __expf(s[i][1] - mnew);
            float p2 = __expf(s[i][2] - mnew);
            float p3 = __expf(s[i][3] - mnew);

            float rs = p0 + p1 + p2 + p3;
            rs += __shfl_xor_sync(0xffffffffu, rs, 1);
            rs += __shfl_xor_sync(0xffffffffu, rs, 2);
            rs += __shfl_xor_sync(0xffffffffu, rs, 4);
            rs += __shfl_xor_sync(0xffffffffu, rs, 8);

            l_r[i] = l_r[i] * alpha + rs;
#pragma unroll
            for (int jj = 0; jj < 8; jj++) o[i][jj] *= alpha;

            Ps[(r0 + i) * LDP + c0s + 0] = p0;
            Ps[(r0 + i) * LDP + c0s + 1] = p1;
            Ps[(r0 + i) * LDP + c0s + 2] = p2;
            Ps[(r0 + i) * LDP + c0s + 3] = p3;
        }
        __syncthreads();

        // O += P @ V   (rows r0.., cols c0v..c0v+7)
#pragma unroll 4
        for (int k = 0; k < 64; k++) {
            float p0 = Ps[(r0 + 0) * LDP + k];
            float p1 = Ps[(r0 + 1) * LDP + k];
            float p2 = Ps[(r0 + 2) * LDP + k];
            float p3 = Ps[(r0 + 3) * LDP + k];
            float4 va = *reinterpret_cast<float4*>(&Vs[k * LDK + c0v]);
            float4 vb = *reinterpret_cast<float4*>(&Vs[k * LDK + c0v + 4]);
            float pr[4] = {p0, p1, p2, p3};
#pragma unroll
            for (int i = 0; i < 4; i++) {
                o[i][0] = fmaf(pr[i], va.x, o[i][0]);
                o[i][1] = fmaf(pr[i], va.y, o[i][1]);
                o[i][2] = fmaf(pr[i], va.z, o[i][2]);
                o[i][3] = fmaf(pr[i], va.w, o[i][3]);
                o[i][4] = fmaf(pr[i], vb.x, o[i][4]);
                o[i][5] = fmaf(pr[i], vb.y, o[i][5]);
                o[i][6] = fmaf(pr[i], vb.z, o[i][6]);
                o[i][7] = fmaf(pr[i], vb.w, o[i][7]);
            }
        }
    }

    // Normalize and write to [B*S, DM] with col = h*128 + c0v
#pragma unroll
    for (int i = 0; i < 4; i++) {
        float inv = 1.0f / l_r[i];
        size_t row = (size_t)(b * SEQ + qt * 64 + r0 + i);
        float4 w0, w1;
        w0.x = o[i][0] * inv; w0.y = o[i][1] * inv;
        w0.z = o[i][2] * inv; w0.w = o[i][3] * inv;
        w1.x = o[i][4] * inv; w1.y = o[i][5] * inv;
        w1.z = o[i][6] * inv; w1.w = o[i][7] * inv;
        float* dst = &attn_out[row * DM + h * DH + c0v];
        *reinterpret_cast<float4*>(dst)     = w0;
        *reinterpret_cast<float4*>(dst + 4) = w1;
    }
}

// ---------------------------------------------------------------------------
extern "C" void kernel_launch(void* const* d_in, const int* in_sizes, int n_in,
                              void* d_out, int out_size)
{
    const float* x     = (const float*)d_in[0];
    const float* w_qkv = (const float*)d_in[1];
    const float* b_qkv = (const float*)d_in[2];
    const float* w_out = (const float*)d_in[3];
    const float* b_out = (const float*)d_in[4];
    float* out = (float*)d_out;

    float* qkv;  float* attn;
    cudaGetSymbolAddress((void**)&qkv,  g_qkv);
    cudaGetSymbolAddress((void**)&attn, g_attn);

    cudaFuncSetAttribute(attn_kernel,
                         cudaFuncAttributeMaxDynamicSharedMemorySize,
                         ATTN_SMEM_BYTES);

    // 1) QKV projection: [8192,2048] @ [2048,6144] + bias
    dim3 g1(QKV_N / 128, MROWS / 128);
    gemm_bias_kernel<<<g1, 256>>>(x, w_qkv, b_qkv, qkv, MROWS, QKV_N, DM);

    // 2) Causal flash attention
    dim3 g2(SEQ / 64, NH, BATCH);
    attn_kernel<<<g2, 256, ATTN_SMEM_BYTES>>>(qkv, attn);

    // 3) Output projection: [8192,2048] @ [2048,2048] + bias
    dim3 g3(DM / 128, MROWS / 128);
    gemm_bias_kernel<<<g3, 256>>>(attn, w_out, b_out, out, MROWS, DM, DM);
}

// round 2
// speedup vs baseline: 1.2423x; 1.2423x over previous
#include <cuda_runtime.h>
#include <cuda_bf16.h>
#include <cstdint>
#include <math.h>

typedef __nv_bfloat16 bf16;

// Problem constants
#define BATCH   4
#define SEQ     2048
#define DM      2048
#define NH      16
#define DH      128
#define MROWS   (BATCH * SEQ)   // 8192
#define QKV_N   (3 * DM)        // 6144

// ---------------------------------------------------------------------------
// Device scratch (allocation-free per harness rules)
// ---------------------------------------------------------------------------
__device__ float g_qkv [(size_t)MROWS * QKV_N];     // [B*S, 3*DM] fp32
__device__ float g_attn[(size_t)MROWS * DM];        // [B*S, DM]   fp32

__device__ bf16 g_xhi[(size_t)MROWS * DM];          // x split
__device__ bf16 g_xlo[(size_t)MROWS * DM];
__device__ bf16 g_ahi[(size_t)MROWS * DM];          // attn-out split
__device__ bf16 g_alo[(size_t)MROWS * DM];
__device__ bf16 g_wqt_hi[(size_t)QKV_N * DM];       // w_qkv^T  [N,K]
__device__ bf16 g_wqt_lo[(size_t)QKV_N * DM];
__device__ bf16 g_wot_hi[(size_t)DM * DM];          // w_out^T  [N,K]
__device__ bf16 g_wot_lo[(size_t)DM * DM];

// ---------------------------------------------------------------------------
// Elementwise fp32 -> (bf16 hi, bf16 lo) split
// ---------------------------------------------------------------------------
__global__ void split_kernel(const float4* __restrict__ src,
                             __nv_bfloat162* __restrict__ hi,
                             __nv_bfloat162* __restrict__ lo,
                             int n4)
{
    int idx = blockIdx.x * blockDim.x + threadIdx.x;
    if (idx >= n4) return;
    float4 v = src[idx];
    bf16 hx = __float2bfloat16(v.x);
    bf16 hy = __float2bfloat16(v.y);
    bf16 hz = __float2bfloat16(v.z);
    bf16 hw = __float2bfloat16(v.w);
    bf16 lx = __float2bfloat16(v.x - __bfloat162float(hx));
    bf16 ly = __float2bfloat16(v.y - __bfloat162float(hy));
    bf16 lz = __float2bfloat16(v.z - __bfloat162float(hz));
    bf16 lw = __float2bfloat16(v.w - __bfloat162float(hw));
    hi[idx * 2 + 0] = __nv_bfloat162(hx, hy);
    hi[idx * 2 + 1] = __nv_bfloat162(hz, hw);
    lo[idx * 2 + 0] = __nv_bfloat162(lx, ly);
    lo[idx * 2 + 1] = __nv_bfloat162(lz, lw);
}

// ---------------------------------------------------------------------------
// Transpose + split: src [K,N] fp32 -> hi/lo [N,K] bf16
// ---------------------------------------------------------------------------
__global__ void transpose_split_kernel(const float* __restrict__ src,
                                       bf16* __restrict__ hi,
                                       bf16* __restrict__ lo,
                                       int K, int N)
{
    __shared__ float t[32][33];
    int nb = blockIdx.x * 32, kb = blockIdx.y * 32;
    int tx = threadIdx.x, ty = threadIdx.y;   // block (32, 8)
#pragma unroll
    for (int i = 0; i < 4; i++)
        t[ty + i * 8][tx] = src[(size_t)(kb + ty + i * 8) * N + nb + tx];
    __syncthreads();
#pragma unroll
    for (int i = 0; i < 4; i++) {
        float v = t[tx][ty + i * 8];                 // (k_local=tx, n_local=ty+i*8)
        size_t o = (size_t)(nb + ty + i * 8) * K + kb + tx;
        bf16 h = __float2bfloat16(v);
        hi[o] = h;
        lo[o] = __float2bfloat16(v - __bfloat162float(h));
    }
}

// ---------------------------------------------------------------------------
// Split-bf16 tensor-core GEMM:
//   C[M,N] = Ahi+Alo [M,K] @ (Bhi+Blo)^T  (B given as [N,K]) + bias[N]
// 3 MMAs per tile-pair: hi*hi + hi*lo + lo*hi (fp32 accumulate).
// Block 128x128xBK32, 8 warps, warp tile 32x64, m16n8k16.
// ---------------------------------------------------------------------------
#define LDT 40                      // bf16 elements per smem row (conflict-free)
#define TILE_ELEMS (128 * LDT)
#define GEMM_SMEM_BYTES (8 * TILE_ELEMS * (int)sizeof(bf16))   // 81920

__device__ __forceinline__ void mma_bf16(float* d, const uint32_t* a, const uint32_t* b)
{
    asm volatile(
        "mma.sync.aligned.m16n8k16.row.col.f32.bf16.bf16.f32 "
        "{%0,%1,%2,%3}, {%4,%5,%6,%7}, {%8,%9}, {%0,%1,%2,%3};\n"
        : "+f"(d[0]), "+f"(d[1]), "+f"(d[2]), "+f"(d[3])
        : "r"(a[0]), "r"(a[1]), "r"(a[2]), "r"(a[3]),
          "r"(b[0]), "r"(b[1]));
}

__device__ __forceinline__ void stage_tile(bf16* __restrict__ s,
                                           const bf16* __restrict__ g,
                                           int row0, int K, int k0, int tid)
{
#pragma unroll
    for (int j = 0; j < 2; j++) {
        int idx = tid + j * 256;
        int r = idx >> 2;
        int c = (idx & 3) << 3;
        *reinterpret_cast<float4*>(&s[r * LDT + c]) =
            *reinterpret_cast<const float4*>(&g[(size_t)(row0 + r) * K + k0 + c]);
    }
}

__global__ __launch_bounds__(256, 1) void gemm_split_kernel(
    const bf16* __restrict__ Ah, const bf16* __restrict__ Al,
    const bf16* __restrict__ Bh, const bf16* __restrict__ Bl,
    const float* __restrict__ bias, float* __restrict__ C,
    int M, int N, int K)
{
    extern __shared__ bf16 smem[];
    bf16* buf[2] = { smem, smem + 4 * TILE_ELEMS };
    // within a buffer: [Ah | Al | Bh | Bl], each TILE_ELEMS

    const int tid  = threadIdx.x;
    const int lane = tid & 31;
    const int warp = tid >> 5;
    const int bm = blockIdx.y * 128;
    const int bn = blockIdx.x * 128;
    const int wm = (warp >> 1) * 32;   // 0,32,64,96
    const int wn = (warp & 1) * 64;    // 0,64
    const int g   = lane >> 2;
    const int tig = lane & 3;

    float acc[2][8][4];
#pragma unroll
    for (int mt = 0; mt < 2; mt++)
#pragma unroll
        for (int nt = 0; nt < 8; nt++)
#pragma unroll
            for (int i = 0; i < 4; i++) acc[mt][nt][i] = 0.0f;

    // prologue: stage tile 0
    stage_tile(buf[0] + 0 * TILE_ELEMS, Ah, bm, K, 0, tid);
    stage_tile(buf[0] + 1 * TILE_ELEMS, Al, bm, K, 0, tid);
    stage_tile(buf[0] + 2 * TILE_ELEMS, Bh, bn, K, 0, tid);
    stage_tile(buf[0] + 3 * TILE_ELEMS, Bl, bn, K, 0, tid);
    __syncthreads();

    const int nk = K >> 5;   // K/32
    for (int t = 0; t < nk; t++) {
        int cur = t & 1;
        int nxt = cur ^ 1;
        if (t + 1 < nk) {
            int k0 = (t + 1) << 5;
            stage_tile(buf[nxt] + 0 * TILE_ELEMS, Ah, bm, K, k0, tid);
            stage_tile(buf[nxt] + 1 * TILE_ELEMS, Al, bm, K, k0, tid);
            stage_tile(buf[nxt] + 2 * TILE_ELEMS, Bh, bn, K, k0, tid);
            stage_tile(buf[nxt] + 3 * TILE_ELEMS, Bl, bn, K, k0, tid);
        }

        const bf16* sAh = buf[cur] + 0 * TILE_ELEMS;
        const bf16* sAl = buf[cur] + 1 * TILE_ELEMS;
        const bf16* sBh = buf[cur] + 2 * TILE_ELEMS;
        const bf16* sBl = buf[cur] + 3 * TILE_ELEMS;

#pragma unroll
        for (int ks = 0; ks < 32; ks += 16) {
            uint32_t ah[2][4], al[2][4], bh[8][2], bl[8][2];
#pragma unroll
            for (int mt = 0; mt < 2; mt++) {
                int rb = wm + mt * 16 + g;
                const bf16* ph = &sAh[rb * LDT + ks + tig * 2];
                const bf16* pl = &sAl[rb * LDT + ks + tig * 2];
                ah[mt][0] = *reinterpret_cast<const uint32_t*>(ph);
                ah[mt][1] = *reinterpret_cast<const uint32_t*>(ph + 8 * LDT);
                ah[mt][2] = *reinterpret_cast<const uint32_t*>(ph + 8);
                ah[mt][3] = *reinterpret_cast<const uint32_t*>(ph + 8 * LDT + 8);
                al[mt][0] = *reinterpret_cast<const uint32_t*>(pl);
                al[mt][1] = *reinterpret_cast<const uint32_t*>(pl + 8 * LDT);
                al[mt][2] = *reinterpret_cast<const uint32_t*>(pl + 8);
                al[mt][3] = *reinterpret_cast<const uint32_t*>(pl + 8 * LDT + 8);
            }
#pragma unroll
            for (int nt = 0; nt < 8; nt++) {
                int cbr = wn + nt * 8 + g;
                const bf16* ph = &sBh[cbr * LDT + ks + tig * 2];
                const bf16* pl = &sBl[cbr * LDT + ks + tig * 2];
                bh[nt][0] = *reinterpret_cast<const uint32_t*>(ph);
                bh[nt][1] = *reinterpret_cast<const uint32_t*>(ph + 8);
                bl[nt][0] = *reinterpret_cast<const uint32_t*>(pl);
                bl[nt][1] = *reinterpret_cast<const uint32_t*>(pl + 8);
            }
#pragma unroll
            for (int mt = 0; mt < 2; mt++)
#pragma unroll
                for (int nt = 0; nt < 8; nt++) {
                    mma_bf16(acc[mt][nt], ah[mt], bh[nt]);
                    mma_bf16(acc[mt][nt], ah[mt], bl[nt]);
                    mma_bf16(acc[mt][nt], al[mt], bh[nt]);
                }
        }
        __syncthreads();
    }

    // epilogue: bias + store
#pragma unroll
    for (int nt = 0; nt < 8; nt++) {
        int col = bn + wn + nt * 8 + tig * 2;
        float b0 = bias[col];
        float b1 = bias[col + 1];
#pragma unroll
        for (int mt = 0; mt < 2; mt++) {
            int row = bm + wm + mt * 16 + g;
            float2 v0, v1;
            v0.x = acc[mt][nt][0] + b0; v0.y = acc[mt][nt][1] + b1;
            v1.x = acc[mt][nt][2] + b0; v1.y = acc[mt][nt][3] + b1;
            *reinterpret_cast<float2*>(&C[(size_t)row * N + col])       = v0;
            *reinterpret_cast<float2*>(&C[(size_t)(row + 8) * N + col]) = v1;
        }
    }
}

// ---------------------------------------------------------------------------
// Flash attention (fp32, causal, online softmax) — unchanged from R0
// ---------------------------------------------------------------------------
#define LDK 132
#define LDP 68
#define ATTN_SMEM_BYTES ((3 * 64 * LDK + 64 * LDP) * (int)sizeof(float))

__global__ __launch_bounds__(256, 1) void attn_kernel(
    const float* __restrict__ qkv, float* __restrict__ attn_out)
{
    extern __shared__ float sm[];
    float* Qs = sm;
    float* Ks = Qs + 64 * LDK;
    float* Vs = Ks + 64 * LDK;
    float* Ps = Vs + 64 * LDK;

    const int qt = blockIdx.x;
    const int h  = blockIdx.y;
    const int b  = blockIdx.z;

    const int tid = threadIdx.x;
    const int tx = tid & 15;
    const int ty = tid >> 4;
    const int r0  = ty * 4;
    const int c0s = tx * 4;
    const int c0v = tx * 8;

    const float scale = 0.08838834764831845f;

    const float* qbase = qkv + (size_t)b * SEQ * QKV_N + h * DH;
    const float* kbase = qbase + DM;
    const float* vbase = qbase + 2 * DM;

    const int lrow = tid >> 5;
    const int lcol = (tid & 31) << 2;
#pragma unroll
    for (int p = 0; p < 8; p++) {
        int r = lrow + p * 8;
        *reinterpret_cast<float4*>(&Qs[r * LDK + lcol]) =
            *reinterpret_cast<const float4*>(
                &qbase[(size_t)(qt * 64 + r) * QKV_N + lcol]);
    }

    float m_r[4], l_r[4], o[4][8];
#pragma unroll
    for (int i = 0; i < 4; i++) {
        m_r[i] = -INFINITY;
        l_r[i] = 0.0f;
#pragma unroll
        for (int j = 0; j < 8; j++) o[i][j] = 0.0f;
    }

    for (int j = 0; j <= qt; j++) {
        __syncthreads();
#pragma unroll
        for (int p = 0; p < 8; p++) {
            int r = lrow + p * 8;
            size_t grow = (size_t)(j * 64 + r) * QKV_N + lcol;
            *reinterpret_cast<float4*>(&Ks[r * LDK + lcol]) =
                *reinterpret_cast<const float4*>(&kbase[grow]);
            *reinterpret_cast<float4*>(&Vs[r * LDK + lcol]) =
                *reinterpret_cast<const float4*>(&vbase[grow]);
        }
        __syncthreads();

        float s[4][4];
#pragma unroll
        for (int i = 0; i < 4; i++)
#pragma unroll
            for (int jj = 0; jj < 4; jj++) s[i][jj] = 0.0f;

#pragma unroll 4
        for (int d = 0; d < DH; d += 4) {
            float4 q0 = *reinterpret_cast<float4*>(&Qs[(r0 + 0) * LDK + d]);
            float4 q1 = *reinterpret_cast<float4*>(&Qs[(r0 + 1) * LDK + d]);
            float4 q2 = *reinterpret_cast<float4*>(&Qs[(r0 + 2) * LDK + d]);
            float4 q3 = *reinterpret_cast<float4*>(&Qs[(r0 + 3) * LDK + d]);
            float4 k0 = *reinterpret_cast<float4*>(&Ks[(c0s + 0) * LDK + d]);
            float4 k1 = *reinterpret_cast<float4*>(&Ks[(c0s + 1) * LDK + d]);
            float4 k2 = *reinterpret_cast<float4*>(&Ks[(c0s + 2) * LDK + d]);
            float4 k3 = *reinterpret_cast<float4*>(&Ks[(c0s + 3) * LDK + d]);
            float4 qv[4] = {q0, q1, q2, q3};
            float4 kv[4] = {k0, k1, k2, k3};
#pragma unroll
            for (int i = 0; i < 4; i++)
#pragma unroll
                for (int jj = 0; jj < 4; jj++) {
                    s[i][jj] = fmaf(qv[i].x, kv[jj].x, s[i][jj]);
                    s[i][jj] = fmaf(qv[i].y, kv[jj].y, s[i][jj]);
                    s[i][jj] = fmaf(qv[i].z, kv[jj].z, s[i][jj]);
                    s[i][jj] = fmaf(qv[i].w, kv[jj].w, s[i][jj]);
                }
        }

#pragma unroll
        for (int i = 0; i < 4; i++)
#pragma unroll
            for (int jj = 0; jj < 4; jj++) {
                s[i][jj] *= scale;
                if (j == qt && (c0s + jj) > (r0 + i)) s[i][jj] = -1e30f;
            }

#pragma unroll
        for (int i = 0; i < 4; i++) {
            float mt = fmaxf(fmaxf(s[i][0], s[i][1]), fmaxf(s[i][2], s[i][3]));
            mt = fmaxf(mt, __shfl_xor_sync(0xffffffffu, mt, 1));
            mt = fmaxf(mt, __shfl_xor_sync(0xffffffffu, mt, 2));
            mt = fmaxf(mt, __shfl_xor_sync(0xffffffffu, mt, 4));
            mt = fmaxf(mt, __shfl_xor_sync(0xffffffffu, mt, 8));

            float mnew  = fmaxf(m_r[i], mt);
            float alpha = __expf(m_r[i] - mnew);
            m_r[i] = mnew;

            float p0 = __expf(s[i][0] - mnew);
            float p1 = __expf(s[i][1] - mnew);
            float p2 = __expf(s[i][2] - mnew);
            float p3 = __expf(s[i][3] - mnew);

            float rs = p0 + p1 + p2 + p3;
            rs += __shfl_xor_sync(0xffffffffu, rs, 1);
            rs += __shfl_xor_sync(0xffffffffu, rs, 2);
            rs += __shfl_xor_sync(0xffffffffu, rs, 4);
            rs += __shfl_xor_sync(0xffffffffu, rs, 8);

            l_r[i] = l_r[i] * alpha + rs;
#pragma unroll
            for (int jj = 0; jj < 8; jj++) o[i][jj] *= alpha;

            Ps[(r0 + i) * LDP + c0s + 0] = p0;
            Ps[(r0 + i) * LDP + c0s + 1] = p1;
            Ps[(r0 + i) * LDP + c0s + 2] = p2;
            Ps[(r0 + i) * LDP + c0s + 3] = p3;
        }
        __syncthreads();

#pragma unroll 4
        for (int k = 0; k < 64; k++) {
            float p0 = Ps[(r0 + 0) * LDP + k];
            float p1 = Ps[(r0 + 1) * LDP + k];
            float p2 = Ps[(r0 + 2) * LDP + k];
            float p3 = Ps[(r0 + 3) * LDP + k];
            float4 va = *reinterpret_cast<float4*>(&Vs[k * LDK + c0v]);
            float4 vb = *reinterpret_cast<float4*>(&Vs[k * LDK + c0v + 4]);
            float pr[4] = {p0, p1, p2, p3};
#pragma unroll
            for (int i = 0; i < 4; i++) {
                o[i][0] = fmaf(pr[i], va.x, o[i][0]);
                o[i][1] = fmaf(pr[i], va.y, o[i][1]);
                o[i][2] = fmaf(pr[i], va.z, o[i][2]);
                o[i][3] = fmaf(pr[i], va.w, o[i][3]);
                o[i][4] = fmaf(pr[i], vb.x, o[i][4]);
                o[i][5] = fmaf(pr[i], vb.y, o[i][5]);
                o[i][6] = fmaf(pr[i], vb.z, o[i][6]);
                o[i][7] = fmaf(pr[i], vb.w, o[i][7]);
            }
        }
    }

#pragma unroll
    for (int i = 0; i < 4; i++) {
        float inv = 1.0f / l_r[i];
        size_t row = (size_t)(b * SEQ + qt * 64 + r0 + i);
        float4 w0, w1;
        w0.x = o[i][0] * inv; w0.y = o[i][1] * inv;
        w0.z = o[i][2] * inv; w0.w = o[i][3] * inv;
        w1.x = o[i][4] * inv; w1.y = o[i][5] * inv;
        w1.z = o[i][6] * inv; w1.w = o[i][7] * inv;
        float* dst = &attn_out[row * DM + h * DH + c0v];
        *reinterpret_cast<float4*>(dst)     = w0;
        *reinterpret_cast<float4*>(dst + 4) = w1;
    }
}

// ---------------------------------------------------------------------------
extern "C" void kernel_launch(void* const* d_in, const int* in_sizes, int n_in,
                              void* d_out, int out_size)
{
    const float* x     = (const float*)d_in[0];
    const float* w_qkv = (const float*)d_in[1];
    const float* b_qkv = (const float*)d_in[2];
    const float* w_out = (const float*)d_in[3];
    const float* b_out = (const float*)d_in[4];
    float* out = (float*)d_out;

    float *qkv, *attn;
    bf16 *xhi, *xlo, *ahi, *alo, *wqh, *wql, *woh, *wol;
    cudaGetSymbolAddress((void**)&qkv,  g_qkv);
    cudaGetSymbolAddress((void**)&attn, g_attn);
    cudaGetSymbolAddress((void**)&xhi,  g_xhi);
    cudaGetSymbolAddress((void**)&xlo,  g_xlo);
    cudaGetSymbolAddress((void**)&ahi,  g_ahi);
    cudaGetSymbolAddress((void**)&alo,  g_alo);
    cudaGetSymbolAddress((void**)&wqh,  g_wqt_hi);
    cudaGetSymbolAddress((void**)&wql,  g_wqt_lo);
    cudaGetSymbolAddress((void**)&woh,  g_wot_hi);
    cudaGetSymbolAddress((void**)&wol,  g_wot_lo);

    cudaFuncSetAttribute(attn_kernel,
                         cudaFuncAttributeMaxDynamicSharedMemorySize,
                         ATTN_SMEM_BYTES);
    cudaFuncSetAttribute(gemm_split_kernel,
                         cudaFuncAttributeMaxDynamicSharedMemorySize,
                         GEMM_SMEM_BYTES);

    // 0a) split x -> bf16 hi/lo
    {
        int n4 = (MROWS * DM) / 4;
        split_kernel<<<n4 / 256, 256>>>((const float4*)x,
                                        (__nv_bfloat162*)xhi, (__nv_bfloat162*)xlo, n4);
    }
    // 0b) transpose+split weights
    {
        dim3 b32(32, 8);
        dim3 gq(QKV_N / 32, DM / 32);
        transpose_split_kernel<<<gq, b32>>>(w_qkv, wqh, wql, DM, QKV_N);
        dim3 go(DM / 32, DM / 32);
        transpose_split_kernel<<<go, b32>>>(w_out, woh, wol, DM, DM);
    }

    // 1) QKV projection (tensor cores, split-bf16)
    {
        dim3 g1(QKV_N / 128, MROWS / 128);
        gemm_split_kernel<<<g1, 256, GEMM_SMEM_BYTES>>>(
            xhi, xlo, wqh, wql, b_qkv, qkv, MROWS, QKV_N, DM);
    }

    // 2) Causal flash attention (fp32)
    {
        dim3 g2(SEQ / 64, NH, BATCH);
        attn_kernel<<<g2, 256, ATTN_SMEM_BYTES>>>(qkv, attn);
    }

    // 3) split attention output, then output projection
    {
        int n4 = (MROWS * DM) / 4;
        split_kernel<<<n4 / 256, 256>>>((const float4*)attn,
                                        (__nv_bfloat162*)ahi, (__nv_bfloat162*)alo, n4);
        dim3 g3(DM / 128, MROWS / 128);
        gemm_split_kernel<<<g3, 256, GEMM_SMEM_BYTES>>>(
            ahi, alo, woh, wol, b_out, out, MROWS, DM, DM);
    }
}

// round 3
// speedup vs baseline: 2.0427x; 1.6443x over previous
#include <cuda_runtime.h>
#include <cuda_bf16.h>
#include <cstdint>
#include <math.h>

typedef __nv_bfloat16 bf16;

// Problem constants
#define BATCH   4
#define SEQ     2048
#define DM      2048
#define NH      16
#define DH      128
#define MROWS   (BATCH * SEQ)   // 8192
#define QKV_N   (3 * DM)        // 6144

// ---------------------------------------------------------------------------
// Device scratch (allocation-free per harness rules)
// ---------------------------------------------------------------------------
__device__ float g_qkv [(size_t)MROWS * QKV_N];     // [B*S, 3*DM] fp32
__device__ float g_attn[(size_t)MROWS * DM];        // [B*S, DM]   fp32

__device__ bf16 g_xhi[(size_t)MROWS * DM];
__device__ bf16 g_xlo[(size_t)MROWS * DM];
__device__ bf16 g_ahi[(size_t)MROWS * DM];
__device__ bf16 g_alo[(size_t)MROWS * DM];
__device__ bf16 g_wqt_hi[(size_t)QKV_N * DM];       // w_qkv^T  [N,K]
__device__ bf16 g_wqt_lo[(size_t)QKV_N * DM];
__device__ bf16 g_wot_hi[(size_t)DM * DM];          // w_out^T  [N,K]
__device__ bf16 g_wot_lo[(size_t)DM * DM];

// ---------------------------------------------------------------------------
// Helpers
// ---------------------------------------------------------------------------
__device__ __forceinline__ uint32_t smem_u32(const void* p) {
    uint32_t a;
    asm("{ .reg .u64 t; cvta.to.shared.u64 t, %1; cvt.u32.u64 %0, t; }"
        : "=r"(a) : "l"(p));
    return a;
}

__device__ __forceinline__ uint32_t pack_bf16(float a, float b) {
    __nv_bfloat162 t = __floats2bfloat162_rn(a, b);
    return *reinterpret_cast<uint32_t*>(&t);
}

__device__ __forceinline__ void ldmatrix_x4(uint32_t& r0, uint32_t& r1,
                                            uint32_t& r2, uint32_t& r3,
                                            uint32_t addr) {
    asm volatile("ldmatrix.sync.aligned.m8n8.x4.shared.b16 {%0,%1,%2,%3}, [%4];\n"
                 : "=r"(r0), "=r"(r1), "=r"(r2), "=r"(r3) : "r"(addr));
}

__device__ __forceinline__ void mma_bf16(float* d, const uint32_t* a, const uint32_t* b)
{
    asm volatile(
        "mma.sync.aligned.m16n8k16.row.col.f32.bf16.bf16.f32 "
        "{%0,%1,%2,%3}, {%4,%5,%6,%7}, {%8,%9}, {%0,%1,%2,%3};\n"
        : "+f"(d[0]), "+f"(d[1]), "+f"(d[2]), "+f"(d[3])
        : "r"(a[0]), "r"(a[1]), "r"(a[2]), "r"(a[3]),
          "r"(b[0]), "r"(b[1]));
}

// ---------------------------------------------------------------------------
// Elementwise fp32 -> (bf16 hi, bf16 lo) split
// ---------------------------------------------------------------------------
__global__ void split_kernel(const float4* __restrict__ src,
                             __nv_bfloat162* __restrict__ hi,
                             __nv_bfloat162* __restrict__ lo,
                             int n4)
{
    int idx = blockIdx.x * blockDim.x + threadIdx.x;
    if (idx >= n4) return;
    float4 v = src[idx];
    bf16 hx = __float2bfloat16(v.x);
    bf16 hy = __float2bfloat16(v.y);
    bf16 hz = __float2bfloat16(v.z);
    bf16 hw = __float2bfloat16(v.w);
    bf16 lx = __float2bfloat16(v.x - __bfloat162float(hx));
    bf16 ly = __float2bfloat16(v.y - __bfloat162float(hy));
    bf16 lz = __float2bfloat16(v.z - __bfloat162float(hz));
    bf16 lw = __float2bfloat16(v.w - __bfloat162float(hw));
    hi[idx * 2 + 0] = __nv_bfloat162(hx, hy);
    hi[idx * 2 + 1] = __nv_bfloat162(hz, hw);
    lo[idx * 2 + 0] = __nv_bfloat162(lx, ly);
    lo[idx * 2 + 1] = __nv_bfloat162(lz, lw);
}

// ---------------------------------------------------------------------------
// Transpose + split: src [K,N] fp32 -> hi/lo [N,K] bf16
// ---------------------------------------------------------------------------
__global__ void transpose_split_kernel(const float* __restrict__ src,
                                       bf16* __restrict__ hi,
                                       bf16* __restrict__ lo,
                                       int K, int N)
{
    __shared__ float t[32][33];
    int nb = blockIdx.x * 32, kb = blockIdx.y * 32;
    int tx = threadIdx.x, ty = threadIdx.y;
#pragma unroll
    for (int i = 0; i < 4; i++)
        t[ty + i * 8][tx] = src[(size_t)(kb + ty + i * 8) * N + nb + tx];
    __syncthreads();
#pragma unroll
    for (int i = 0; i < 4; i++) {
        float v = t[tx][ty + i * 8];
        size_t o = (size_t)(nb + ty + i * 8) * K + kb + tx;
        bf16 h = __float2bfloat16(v);
        hi[o] = h;
        lo[o] = __float2bfloat16(v - __bfloat162float(h));
    }
}

// ---------------------------------------------------------------------------
// Split-bf16 tensor-core GEMM (unchanged from R2)
// ---------------------------------------------------------------------------
#define LDT 40
#define TILE_ELEMS (128 * LDT)
#define GEMM_SMEM_BYTES (8 * TILE_ELEMS * (int)sizeof(bf16))

__device__ __forceinline__ void stage_tile(bf16* __restrict__ s,
                                           const bf16* __restrict__ g,
                                           int row0, int K, int k0, int tid)
{
#pragma unroll
    for (int j = 0; j < 2; j++) {
        int idx = tid + j * 256;
        int r = idx >> 2;
        int c = (idx & 3) << 3;
        *reinterpret_cast<float4*>(&s[r * LDT + c]) =
            *reinterpret_cast<const float4*>(&g[(size_t)(row0 + r) * K + k0 + c]);
    }
}

__global__ __launch_bounds__(256, 1) void gemm_split_kernel(
    const bf16* __restrict__ Ah, const bf16* __restrict__ Al,
    const bf16* __restrict__ Bh, const bf16* __restrict__ Bl,
    const float* __restrict__ bias, float* __restrict__ C,
    int M, int N, int K)
{
    extern __shared__ bf16 smem[];
    bf16* buf[2] = { smem, smem + 4 * TILE_ELEMS };

    const int tid  = threadIdx.x;
    const int lane = tid & 31;
    const int warp = tid >> 5;
    const int bm = blockIdx.y * 128;
    const int bn = blockIdx.x * 128;
    const int wm = (warp >> 1) * 32;
    const int wn = (warp & 1) * 64;
    const int g   = lane >> 2;
    const int tig = lane & 3;

    float acc[2][8][4];
#pragma unroll
    for (int mt = 0; mt < 2; mt++)
#pragma unroll
        for (int nt = 0; nt < 8; nt++)
#pragma unroll
            for (int i = 0; i < 4; i++) acc[mt][nt][i] = 0.0f;

    stage_tile(buf[0] + 0 * TILE_ELEMS, Ah, bm, K, 0, tid);
    stage_tile(buf[0] + 1 * TILE_ELEMS, Al, bm, K, 0, tid);
    stage_tile(buf[0] + 2 * TILE_ELEMS, Bh, bn, K, 0, tid);
    stage_tile(buf[0] + 3 * TILE_ELEMS, Bl, bn, K, 0, tid);
    __syncthreads();

    const int nk = K >> 5;
    for (int t = 0; t < nk; t++) {
        int cur = t & 1;
        int nxt = cur ^ 1;
        if (t + 1 < nk) {
            int k0 = (t + 1) << 5;
            stage_tile(buf[nxt] + 0 * TILE_ELEMS, Ah, bm, K, k0, tid);
            stage_tile(buf[nxt] + 1 * TILE_ELEMS, Al, bm, K, k0, tid);
            stage_tile(buf[nxt] + 2 * TILE_ELEMS, Bh, bn, K, k0, tid);
            stage_tile(buf[nxt] + 3 * TILE_ELEMS, Bl, bn, K, k0, tid);
        }

        const bf16* sAh = buf[cur] + 0 * TILE_ELEMS;
        const bf16* sAl = buf[cur] + 1 * TILE_ELEMS;
        const bf16* sBh = buf[cur] + 2 * TILE_ELEMS;
        const bf16* sBl = buf[cur] + 3 * TILE_ELEMS;

#pragma unroll
        for (int ks = 0; ks < 32; ks += 16) {
            uint32_t ah[2][4], al[2][4], bh[8][2], bl[8][2];
#pragma unroll
            for (int mt = 0; mt < 2; mt++) {
                int rb = wm + mt * 16 + g;
                const bf16* ph = &sAh[rb * LDT + ks + tig * 2];
                const bf16* pl = &sAl[rb * LDT + ks + tig * 2];
                ah[mt][0] = *reinterpret_cast<const uint32_t*>(ph);
                ah[mt][1] = *reinterpret_cast<const uint32_t*>(ph + 8 * LDT);
                ah[mt][2] = *reinterpret_cast<const uint32_t*>(ph + 8);
                ah[mt][3] = *reinterpret_cast<const uint32_t*>(ph + 8 * LDT + 8);
                al[mt][0] = *reinterpret_cast<const uint32_t*>(pl);
                al[mt][1] = *reinterpret_cast<const uint32_t*>(pl + 8 * LDT);
                al[mt][2] = *reinterpret_cast<const uint32_t*>(pl + 8);
                al[mt][3] = *reinterpret_cast<const uint32_t*>(pl + 8 * LDT + 8);
            }
#pragma unroll
            for (int nt = 0; nt < 8; nt++) {
                int cbr = wn + nt * 8 + g;
                const bf16* ph = &sBh[cbr * LDT + ks + tig * 2];
                const bf16* pl = &sBl[cbr * LDT + ks + tig * 2];
                bh[nt][0] = *reinterpret_cast<const uint32_t*>(ph);
                bh[nt][1] = *reinterpret_cast<const uint32_t*>(ph + 8);
                bl[nt][0] = *reinterpret_cast<const uint32_t*>(pl);
                bl[nt][1] = *reinterpret_cast<const uint32_t*>(pl + 8);
            }
#pragma unroll
            for (int mt = 0; mt < 2; mt++)
#pragma unroll
                for (int nt = 0; nt < 8; nt++) {
                    mma_bf16(acc[mt][nt], ah[mt], bh[nt]);
                    mma_bf16(acc[mt][nt], ah[mt], bl[nt]);
                    mma_bf16(acc[mt][nt], al[mt], bh[nt]);
                }
        }
        __syncthreads();
    }

#pragma unroll
    for (int nt = 0; nt < 8; nt++) {
        int col = bn + wn + nt * 8 + tig * 2;
        float b0 = bias[col];
        float b1 = bias[col + 1];
#pragma unroll
        for (int mt = 0; mt < 2; mt++) {
            int row = bm + wm + mt * 16 + g;
            float2 v0, v1;
            v0.x = acc[mt][nt][0] + b0; v0.y = acc[mt][nt][1] + b1;
            v1.x = acc[mt][nt][2] + b0; v1.y = acc[mt][nt][3] + b1;
            *reinterpret_cast<float2*>(&C[(size_t)row * N + col])       = v0;
            *reinterpret_cast<float2*>(&C[(size_t)(row + 8) * N + col]) = v1;
        }
    }
}

// ---------------------------------------------------------------------------
// Tensor-core flash attention (split-bf16, causal, online softmax).
// CTA = (b, h, 128-row Q tile); 8 warps, each owns 16 Q rows.
// KV tiles of 64 rows. Q/K split hi/lo in smem; V split + transposed in smem.
// P split hi/lo in registers (FA2 fragment reuse).
// ---------------------------------------------------------------------------
#define LDQ 136                  // bf16 stride for Q/K smem rows (k-major)
#define LDV 72                   // bf16 stride for Vt smem rows (n-major)
#define QTILE 128
#define KTILE 64

#define SM_QHI 0
#define SM_QLO (SM_QHI + QTILE * LDQ)
#define SM_KHI (SM_QLO + QTILE * LDQ)
#define SM_KLO (SM_KHI + KTILE * LDQ)
#define SM_VTHI (SM_KLO + KTILE * LDQ)
#define SM_VTLO (SM_VTHI + DH * LDV)
#define ATTN_SMEM_ELEMS (SM_VTLO + DH * LDV)
#define ATTN_SMEM_BYTES (ATTN_SMEM_ELEMS * (int)sizeof(bf16))   // 141312

__global__ __launch_bounds__(256, 1) void attn_tc_kernel(
    const float* __restrict__ qkv, float* __restrict__ attn_out)
{
    extern __shared__ bf16 asmem[];
    const uint32_t sbase = smem_u32(asmem);

    const int qt = blockIdx.x;      // 0..15
    const int h  = blockIdx.y;
    const int b  = blockIdx.z;

    const int tid  = threadIdx.x;
    const int lane = tid & 31;
    const int warp = tid >> 5;
    const int g    = lane >> 2;
    const int tig  = lane & 3;
    const int wr   = warp * 16;     // warp's Q-row base within tile

    // ldmatrix lane->row/col offsets
    const int a_row = (lane & 7) + ((lane >> 3) & 1) * 8;   // A frags (x4, m16k16)
    const int a_col = (lane >> 4) * 8;
    const int b_row = ((lane >> 4) * 8) + (lane & 7);       // B frags (x4, n16k16)
    const int b_col = ((lane >> 3) & 1) * 8;

    const float scale = 0.08838834764831845f;   // 1/sqrt(128)

    const float* qbase = qkv + (size_t)b * SEQ * QKV_N + h * DH;
    const float* kbase = qbase + DM;
    const float* vbase = qbase + 2 * DM;

    // ---- Load + split Q tile (scale folded in) ----
    {
        bf16* qhi = asmem + SM_QHI;
        bf16* qlo = asmem + SM_QLO;
#pragma unroll
        for (int p = 0; p < 16; p++) {
            int idx = tid + p * 256;
            int r = idx >> 5;
            int c = (idx & 31) << 2;
            float4 v = *reinterpret_cast<const float4*>(
                &qbase[(size_t)(qt * QTILE + r) * QKV_N + c]);
            v.x *= scale; v.y *= scale; v.z *= scale; v.w *= scale;
            bf16 h0 = __float2bfloat16(v.x), h1 = __float2bfloat16(v.y);
            bf16 h2 = __float2bfloat16(v.z), h3 = __float2bfloat16(v.w);
            uint32_t* dsthi = reinterpret_cast<uint32_t*>(&qhi[r * LDQ + c]);
            uint32_t* dstlo = reinterpret_cast<uint32_t*>(&qlo[r * LDQ + c]);
            dsthi[0] = pack_bf16(v.x, v.y);
            dsthi[1] = pack_bf16(v.z, v.w);
            dstlo[0] = pack_bf16(v.x - __bfloat162float(h0), v.y - __bfloat162float(h1));
            dstlo[1] = pack_bf16(v.z - __bfloat162float(h2), v.w - __bfloat162float(h3));
        }
    }

    float m0 = -INFINITY, m1 = -INFINITY, l0 = 0.0f, l1 = 0.0f;
    float o[16][4];
#pragma unroll
    for (int nt = 0; nt < 16; nt++)
#pragma unroll
        for (int i = 0; i < 4; i++) o[nt][i] = 0.0f;

    const int rowg  = qt * QTILE + wr + g;
    const int rowg8 = rowg + 8;
    const int njt = 2 * qt + 2;

    for (int j = 0; j < njt; j++) {
        __syncthreads();
        // ---- Load + split K tile (k-major) ----
        {
            bf16* khi = asmem + SM_KHI;
            bf16* klo = asmem + SM_KLO;
#pragma unroll
            for (int p = 0; p < 8; p++) {
                int idx = tid + p * 256;
                int r = idx >> 5;
                int c = (idx & 31) << 2;
                float4 v = *reinterpret_cast<const float4*>(
                    &kbase[(size_t)(j * KTILE + r) * QKV_N + c]);
                bf16 h0 = __float2bfloat16(v.x), h1 = __float2bfloat16(v.y);
                bf16 h2 = __float2bfloat16(v.z), h3 = __float2bfloat16(v.w);
                uint32_t* dsthi = reinterpret_cast<uint32_t*>(&khi[r * LDQ + c]);
                uint32_t* dstlo = reinterpret_cast<uint32_t*>(&klo[r * LDQ + c]);
                dsthi[0] = pack_bf16(v.x, v.y);
                dsthi[1] = pack_bf16(v.z, v.w);
                dstlo[0] = pack_bf16(v.x - __bfloat162float(h0), v.y - __bfloat162float(h1));
                dstlo[1] = pack_bf16(v.z - __bfloat162float(h2), v.w - __bfloat162float(h3));
            }
        }
        // ---- Load + split V tile transposed: Vt[n=dh][k=seq] ----
        {
            bf16* vthi = asmem + SM_VTHI;
            bf16* vtlo = asmem + SM_VTLO;
#pragma unroll
            for (int p = 0; p < 16; p++) {
                int it = tid + p * 256;
                int n  = it & 127;
                int k0 = (it >> 7) << 1;
                float v0 = vbase[(size_t)(j * KTILE + k0)     * QKV_N + n];
                float v1 = vbase[(size_t)(j * KTILE + k0 + 1) * QKV_N + n];
                bf16 h0 = __float2bfloat16(v0), h1 = __float2bfloat16(v1);
                *reinterpret_cast<uint32_t*>(&vthi[n * LDV + k0]) = pack_bf16(v0, v1);
                *reinterpret_cast<uint32_t*>(&vtlo[n * LDV + k0]) =
                    pack_bf16(v0 - __bfloat162float(h0), v1 - __bfloat162float(h1));
            }
        }
        __syncthreads();

        // skip fully-masked warp blocks
        if (j * KTILE > qt * QTILE + wr + 15) continue;

        // ---- S = Q @ K^T (split: hh + hl + lh) ----
        float s[8][4];
#pragma unroll
        for (int nt = 0; nt < 8; nt++)
#pragma unroll
            for (int i = 0; i < 4; i++) s[nt][i] = 0.0f;

        const uint32_t qhi_a = sbase + (uint32_t)(SM_QHI + (wr + a_row) * LDQ + a_col) * 2;
        const uint32_t qlo_a = sbase + (uint32_t)(SM_QLO + (wr + a_row) * LDQ + a_col) * 2;
        const uint32_t khi_b = sbase + (uint32_t)(SM_KHI + b_row * LDQ + b_col) * 2;
        const uint32_t klo_b = sbase + (uint32_t)(SM_KLO + b_row * LDQ + b_col) * 2;

#pragma unroll
        for (int ks = 0; ks < 8; ks++) {
            uint32_t ah[4], al[4];
            ldmatrix_x4(ah[0], ah[1], ah[2], ah[3], qhi_a + ks * 32);
            ldmatrix_x4(al[0], al[1], al[2], al[3], qlo_a + ks * 32);
#pragma unroll
            for (int ntp = 0; ntp < 4; ntp++) {
                uint32_t bh[4], bl[4];
                ldmatrix_x4(bh[0], bh[1], bh[2], bh[3],
                            khi_b + (uint32_t)(ntp * 16 * LDQ + ks * 16) * 2);
                ldmatrix_x4(bl[0], bl[1], bl[2], bl[3],
                            klo_b + (uint32_t)(ntp * 16 * LDQ + ks * 16) * 2);
                mma_bf16(s[2 * ntp],     ah, bh);
                mma_bf16(s[2 * ntp],     ah, bl);
                mma_bf16(s[2 * ntp],     al, bh);
                mma_bf16(s[2 * ntp + 1], ah, bh + 2);
                mma_bf16(s[2 * ntp + 1], ah, bl + 2);
                mma_bf16(s[2 * ntp + 1], al, bh + 2);
            }
        }

        // ---- causal mask ----
        const int jc = j * KTILE;
        if (jc + KTILE - 1 > rowg) {
#pragma unroll
            for (int nt = 0; nt < 8; nt++) {
                int c0 = jc + nt * 8 + tig * 2;
                if (c0     > rowg) s[nt][0] = -1e30f;
                if (c0 + 1 > rowg) s[nt][1] = -1e30f;
            }
        }
        if (jc + KTILE - 1 > rowg8) {
#pragma unroll
            for (int nt = 0; nt < 8; nt++) {
                int c0 = jc + nt * 8 + tig * 2;
                if (c0     > rowg8) s[nt][2] = -1e30f;
                if (c0 + 1 > rowg8) s[nt][3] = -1e30f;
            }
        }

        // ---- online softmax (registers + 2 shfls per row) ----
        float mt0 = -1e30f, mt1 = -1e30f;
#pragma unroll
        for (int nt = 0; nt < 8; nt++) {
            mt0 = fmaxf(mt0, fmaxf(s[nt][0], s[nt][1]));
            mt1 = fmaxf(mt1, fmaxf(s[nt][2], s[nt][3]));
        }
        mt0 = fmaxf(mt0, __shfl_xor_sync(0xffffffffu, mt0, 1));
        mt0 = fmaxf(mt0, __shfl_xor_sync(0xffffffffu, mt0, 2));
        mt1 = fmaxf(mt1, __shfl_xor_sync(0xffffffffu, mt1, 1));
        mt1 = fmaxf(mt1, __shfl_xor_sync(0xffffffffu, mt1, 2));

        float mn0 = fmaxf(m0, mt0);
        float mn1 = fmaxf(m1, mt1);
        float al0 = __expf(m0 - mn0);
        float al1 = __expf(m1 - mn1);
        m0 = mn0; m1 = mn1;

        float rs0 = 0.0f, rs1 = 0.0f;
#pragma unroll
        for (int nt = 0; nt < 8; nt++) {
            s[nt][0] = __expf(s[nt][0] - mn0); rs0 += s[nt][0];
            s[nt][1] = __expf(s[nt][1] - mn0); rs0 += s[nt][1];
            s[nt][2] = __expf(s[nt][2] - mn1); rs1 += s[nt][2];
            s[nt][3] = __expf(s[nt][3] - mn1); rs1 += s[nt][3];
        }
        rs0 += __shfl_xor_sync(0xffffffffu, rs0, 1);
        rs0 += __shfl_xor_sync(0xffffffffu, rs0, 2);
        rs1 += __shfl_xor_sync(0xffffffffu, rs1, 1);
        rs1 += __shfl_xor_sync(0xffffffffu, rs1, 2);

        l0 = l0 * al0 + rs0;
        l1 = l1 * al1 + rs1;
#pragma unroll
        for (int nt = 0; nt < 16; nt++) {
            o[nt][0] *= al0; o[nt][1] *= al0;
            o[nt][2] *= al1; o[nt][3] *= al1;
        }

        // ---- O += P @ V (P split in registers; Vt split in smem) ----
        const uint32_t vhi_b = sbase + (uint32_t)(SM_VTHI + b_row * LDV + b_col) * 2;
        const uint32_t vlo_b = sbase + (uint32_t)(SM_VTLO + b_row * LDV + b_col) * 2;

#pragma unroll
        for (int ks = 0; ks < 4; ks++) {
            // pack P fragments (hi/lo) from S registers
            uint32_t ph[4], pl[4];
#pragma unroll
            for (int half = 0; half < 2; half++) {
                float p0 = s[2 * ks + half][0];
                float p1 = s[2 * ks + half][1];
                float p2 = s[2 * ks + half][2];
                float p3 = s[2 * ks + half][3];
                bf16 h0 = __float2bfloat16(p0), h1 = __float2bfloat16(p1);
                bf16 h2 = __float2bfloat16(p2), h3 = __float2bfloat16(p3);
                ph[0 + 2 * half] = pack_bf16(p0, p1);
                ph[1 + 2 * half] = pack_bf16(p2, p3);
                pl[0 + 2 * half] = pack_bf16(p0 - __bfloat162float(h0),
                                             p1 - __bfloat162float(h1));
                pl[1 + 2 * half] = pack_bf16(p2 - __bfloat162float(h2),
                                             p3 - __bfloat162float(h3));
            }
            // fragment order: a0,a1 = rows g,g+8 of k-lo half; a2,a3 = k-hi half
            uint32_t ahf[4] = { ph[0], ph[1], ph[2], ph[3] };
            uint32_t alf[4] = { pl[0], pl[1], pl[2], pl[3] };

#pragma unroll
            for (int ntp = 0; ntp < 8; ntp++) {
                uint32_t bh[4], bl[4];
                ldmatrix_x4(bh[0], bh[1], bh[2], bh[3],
                            vhi_b + (uint32_t)(ntp * 16 * LDV + ks * 16) * 2);
                ldmatrix_x4(bl[0], bl[1], bl[2], bl[3],
                            vlo_b + (uint32_t)(ntp * 16 * LDV + ks * 16) * 2);
                mma_bf16(o[2 * ntp],     ahf, bh);
                mma_bf16(o[2 * ntp],     ahf, bl);
                mma_bf16(o[2 * ntp],     alf, bh);
                mma_bf16(o[2 * ntp + 1], ahf, bh + 2);
                mma_bf16(o[2 * ntp + 1], ahf, bl + 2);
                mma_bf16(o[2 * ntp + 1], alf, bh + 2);
            }
        }
    }

    // ---- normalize + store ----
    const float inv0 = 1.0f / l0;
    const float inv1 = 1.0f / l1;
#pragma unroll
    for (int nt = 0; nt < 16; nt++) {
        int col = h * DH + nt * 8 + tig * 2;
        size_t r0w = (size_t)(b * SEQ + rowg)  * DM + col;
        size_t r1w = (size_t)(b * SEQ + rowg8) * DM + col;
        float2 v0, v1;
        v0.x = o[nt][0] * inv0; v0.y = o[nt][1] * inv0;
        v1.x = o[nt][2] * inv1; v1.y = o[nt][3] * inv1;
        *reinterpret_cast<float2*>(&attn_out[r0w]) = v0;
        *reinterpret_cast<float2*>(&attn_out[r1w]) = v1;
    }
}

// ---------------------------------------------------------------------------
extern "C" void kernel_launch(void* const* d_in, const int* in_sizes, int n_in,
                              void* d_out, int out_size)
{
    const float* x     = (const float*)d_in[0];
    const float* w_qkv = (const float*)d_in[1];
    const float* b_qkv = (const float*)d_in[2];
    const float* w_out = (const float*)d_in[3];
    const float* b_out = (const float*)d_in[4];
    float* out = (float*)d_out;

    float *qkv, *attn;
    bf16 *xhi, *xlo, *ahi, *alo, *wqh, *wql, *woh, *wol;
    cudaGetSymbolAddress((void**)&qkv,  g_qkv);
    cudaGetSymbolAddress((void**)&attn, g_attn);
    cudaGetSymbolAddress((void**)&xhi,  g_xhi);
    cudaGetSymbolAddress((void**)&xlo,  g_xlo);
    cudaGetSymbolAddress((void**)&ahi,  g_ahi);
    cudaGetSymbolAddress((void**)&alo,  g_alo);
    cudaGetSymbolAddress((void**)&wqh,  g_wqt_hi);
    cudaGetSymbolAddress((void**)&wql,  g_wqt_lo);
    cudaGetSymbolAddress((void**)&woh,  g_wot_hi);
    cudaGetSymbolAddress((void**)&wol,  g_wot_lo);

    cudaFuncSetAttribute(attn_tc_kernel,
                         cudaFuncAttributeMaxDynamicSharedMemorySize,
                         ATTN_SMEM_BYTES);
    cudaFuncSetAttribute(gemm_split_kernel,
                         cudaFuncAttributeMaxDynamicSharedMemorySize,
                         GEMM_SMEM_BYTES);

    // 0a) split x -> bf16 hi/lo
    {
        int n4 = (MROWS * DM) / 4;
        split_kernel<<<n4 / 256, 256>>>((const float4*)x,
                                        (__nv_bfloat162*)xhi, (__nv_bfloat162*)xlo, n4);
    }
    // 0b) transpose+split weights
    {
        dim3 b32(32, 8);
        dim3 gq(QKV_N / 32, DM / 32);
        transpose_split_kernel<<<gq, b32>>>(w_qkv, wqh, wql, DM, QKV_N);
        dim3 go(DM / 32, DM / 32);
        transpose_split_kernel<<<go, b32>>>(w_out, woh, wol, DM, DM);
    }

    // 1) QKV projection (tensor cores, split-bf16)
    {
        dim3 g1(QKV_N / 128, MROWS / 128);
        gemm_split_kernel<<<g1, 256, GEMM_SMEM_BYTES>>>(
            xhi, xlo, wqh, wql, b_qkv, qkv, MROWS, QKV_N, DM);
    }

    // 2) Causal flash attention (tensor cores, split-bf16)
    {
        dim3 g2(SEQ / QTILE, NH, BATCH);
        attn_tc_kernel<<<g2, 256, ATTN_SMEM_BYTES>>>(qkv, attn);
    }

    // 3) split attention output, then output projection
    {
        int n4 = (MROWS * DM) / 4;
        split_kernel<<<n4 / 256, 256>>>((const float4*)attn,
                                        (__nv_bfloat162*)ahi, (__nv_bfloat162*)alo, n4);
        dim3 g3(DM / 128, MROWS / 128);
        gemm_split_kernel<<<g3, 256, GEMM_SMEM_BYTES>>>(
            ahi, alo, woh, wol, b_out, out, MROWS, DM, DM);
    }
}

// round 4
// speedup vs baseline: 2.7385x; 1.3407x over previous
#include <cuda_runtime.h>
#include <cuda_bf16.h>
#include <cstdint>
#include <math.h>

typedef __nv_bfloat16 bf16;

// Problem constants
#define BATCH   4
#define SEQ     2048
#define DM      2048
#define NH      16
#define DH      128
#define MROWS   (BATCH * SEQ)   // 8192
#define QKV_N   (3 * DM)        // 6144

// ---------------------------------------------------------------------------
// Device scratch (allocation-free per harness rules)
// ---------------------------------------------------------------------------
__device__ bf16 g_xhi[(size_t)MROWS * DM];
__device__ bf16 g_xlo[(size_t)MROWS * DM];
__device__ bf16 g_qkvhi[(size_t)MROWS * QKV_N];     // split qkv (GEMM1 out)
__device__ bf16 g_qkvlo[(size_t)MROWS * QKV_N];
__device__ bf16 g_ahi[(size_t)MROWS * DM];          // split attn out
__device__ bf16 g_alo[(size_t)MROWS * DM];
__device__ bf16 g_wqt_hi[(size_t)QKV_N * DM];       // w_qkv^T  [N,K]
__device__ bf16 g_wqt_lo[(size_t)QKV_N * DM];
__device__ bf16 g_wot_hi[(size_t)DM * DM];          // w_out^T  [N,K]
__device__ bf16 g_wot_lo[(size_t)DM * DM];

// ---------------------------------------------------------------------------
// Helpers
// ---------------------------------------------------------------------------
__device__ __forceinline__ uint32_t smem_u32(const void* p) {
    uint32_t a;
    asm("{ .reg .u64 t; cvta.to.shared.u64 t, %1; cvt.u32.u64 %0, t; }"
        : "=r"(a) : "l"(p));
    return a;
}

__device__ __forceinline__ uint32_t pack_bf16(float a, float b) {
    __nv_bfloat162 t = __floats2bfloat162_rn(a, b);
    return *reinterpret_cast<uint32_t*>(&t);
}

__device__ __forceinline__ void cp16(uint32_t dst, const void* src) {
    asm volatile("cp.async.cg.shared.global [%0], [%1], 16;\n"
                 :: "r"(dst), "l"(src));
}
#define CP_COMMIT() asm volatile("cp.async.commit_group;\n")
#define CP_WAIT(N)  asm volatile("cp.async.wait_group %0;\n" :: "n"(N))

__device__ __forceinline__ void ldmatrix_x4(uint32_t& r0, uint32_t& r1,
                                            uint32_t& r2, uint32_t& r3,
                                            uint32_t addr) {
    asm volatile("ldmatrix.sync.aligned.m8n8.x4.shared.b16 {%0,%1,%2,%3}, [%4];\n"
                 : "=r"(r0), "=r"(r1), "=r"(r2), "=r"(r3) : "r"(addr));
}
__device__ __forceinline__ void ldmatrix_x4_trans(uint32_t& r0, uint32_t& r1,
                                                  uint32_t& r2, uint32_t& r3,
                                                  uint32_t addr) {
    asm volatile("ldmatrix.sync.aligned.m8n8.x4.trans.shared.b16 {%0,%1,%2,%3}, [%4];\n"
                 : "=r"(r0), "=r"(r1), "=r"(r2), "=r"(r3) : "r"(addr));
}

__device__ __forceinline__ void mma_bf16(float* d, const uint32_t* a, const uint32_t* b)
{
    asm volatile(
        "mma.sync.aligned.m16n8k16.row.col.f32.bf16.bf16.f32 "
        "{%0,%1,%2,%3}, {%4,%5,%6,%7}, {%8,%9}, {%0,%1,%2,%3};\n"
        : "+f"(d[0]), "+f"(d[1]), "+f"(d[2]), "+f"(d[3])
        : "r"(a[0]), "r"(a[1]), "r"(a[2]), "r"(a[3]),
          "r"(b[0]), "r"(b[1]));
}

// ---------------------------------------------------------------------------
// Elementwise fp32 -> (bf16 hi, bf16 lo) split
// ---------------------------------------------------------------------------
__global__ void split_kernel(const float4* __restrict__ src,
                             __nv_bfloat162* __restrict__ hi,
                             __nv_bfloat162* __restrict__ lo,
                             int n4)
{
    int idx = blockIdx.x * blockDim.x + threadIdx.x;
    if (idx >= n4) return;
    float4 v = src[idx];
    bf16 hx = __float2bfloat16(v.x);
    bf16 hy = __float2bfloat16(v.y);
    bf16 hz = __float2bfloat16(v.z);
    bf16 hw = __float2bfloat16(v.w);
    bf16 lx = __float2bfloat16(v.x - __bfloat162float(hx));
    bf16 ly = __float2bfloat16(v.y - __bfloat162float(hy));
    bf16 lz = __float2bfloat16(v.z - __bfloat162float(hz));
    bf16 lw = __float2bfloat16(v.w - __bfloat162float(hw));
    hi[idx * 2 + 0] = __nv_bfloat162(hx, hy);
    hi[idx * 2 + 1] = __nv_bfloat162(hz, hw);
    lo[idx * 2 + 0] = __nv_bfloat162(lx, ly);
    lo[idx * 2 + 1] = __nv_bfloat162(lz, lw);
}

// ---------------------------------------------------------------------------
// Transpose + split: src [K,N] fp32 -> hi/lo [N,K] bf16
// ---------------------------------------------------------------------------
__global__ void transpose_split_kernel(const float* __restrict__ src,
                                       bf16* __restrict__ hi,
                                       bf16* __restrict__ lo,
                                       int K, int N)
{
    __shared__ float t[32][33];
    int nb = blockIdx.x * 32, kb = blockIdx.y * 32;
    int tx = threadIdx.x, ty = threadIdx.y;
#pragma unroll
    for (int i = 0; i < 4; i++)
        t[ty + i * 8][tx] = src[(size_t)(kb + ty + i * 8) * N + nb + tx];
    __syncthreads();
#pragma unroll
    for (int i = 0; i < 4; i++) {
        float v = t[tx][ty + i * 8];
        size_t o = (size_t)(nb + ty + i * 8) * K + kb + tx;
        bf16 h = __float2bfloat16(v);
        hi[o] = h;
        lo[o] = __float2bfloat16(v - __bfloat162float(h));
    }
}

// ---------------------------------------------------------------------------
// Split-bf16 tensor-core GEMM with cp.async 4-stage pipeline + ldmatrix.
//   C[M,N] = (Ah+Al)[M,K] @ (Bh+Bl)^T (B stored [N,K]) + bias[N]
// Block 128x128x32, 8 warps (warp tile 32x64), m16n8k16, 3 MMAs per pair.
// SPLIT_OUT: emit bf16 hi/lo split instead of fp32.
// ---------------------------------------------------------------------------
#define LDT 40
#define G_TILE (128 * LDT)               // elems per operand tile (5120)
#define G_STAGE_E (4 * G_TILE)           // elems per stage (20480)
#define G_STAGES 4
#define GEMM_SMEM_BYTES (G_STAGES * G_STAGE_E * 2)   // 163840

template<bool SPLIT_OUT>
__global__ __launch_bounds__(256, 1) void gemm_tc_kernel(
    const bf16* __restrict__ Ah, const bf16* __restrict__ Al,
    const bf16* __restrict__ Bh, const bf16* __restrict__ Bl,
    const float* __restrict__ bias,
    float* __restrict__ Cf, bf16* __restrict__ Chi, bf16* __restrict__ Clo,
    int M, int N, int K)
{
    extern __shared__ bf16 gsm[];
    const uint32_t sb = smem_u32(gsm);

    const int tid  = threadIdx.x;
    const int lane = tid & 31;
    const int warp = tid >> 5;
    const int bm = blockIdx.y * 128;
    const int bn = blockIdx.x * 128;
    const int wm = (warp >> 1) * 32;
    const int wn = (warp & 1) * 64;
    const int g   = lane >> 2;
    const int tig = lane & 3;

    const int a_r = lane & 15;
    const int a_c = (lane >> 4) * 8;
    const int b_r = ((lane >> 4) * 8) + (lane & 7);
    const int b_c = ((lane >> 3) & 1) * 8;

    const bf16* gsrc0 = Ah + (size_t)bm * K;
    const bf16* gsrc1 = Al + (size_t)bm * K;
    const bf16* gsrc2 = Bh + (size_t)bn * K;
    const bf16* gsrc3 = Bl + (size_t)bn * K;

    const int nk = K >> 5;

    auto issue = [&](int t) {
        if (t < nk) {
            int k0 = t << 5;
            uint32_t stb = sb + (uint32_t)((t & (G_STAGES - 1)) * G_STAGE_E) * 2;
#pragma unroll
            for (int jj = 0; jj < 8; jj++) {
                const int tile = jj >> 1;
                int q  = tid + (jj & 1) * 256;
                int r  = q >> 2;
                int ch = (q & 3) << 3;
                const bf16* src =
                    (tile == 0 ? gsrc0 : tile == 1 ? gsrc1 : tile == 2 ? gsrc2 : gsrc3)
                    + (size_t)r * K + k0 + ch;
                cp16(stb + (uint32_t)(tile * G_TILE + r * LDT + ch) * 2, src);
            }
        }
        CP_COMMIT();
    };

    issue(0); issue(1); issue(2);

    float acc[2][8][4];
#pragma unroll
    for (int mt = 0; mt < 2; mt++)
#pragma unroll
        for (int nt = 0; nt < 8; nt++)
#pragma unroll
            for (int i = 0; i < 4; i++) acc[mt][nt][i] = 0.0f;

    for (int t = 0; t < nk; t++) {
        issue(t + 3);
        CP_WAIT(3);
        __syncthreads();
        const uint32_t cb = sb + (uint32_t)((t & (G_STAGES - 1)) * G_STAGE_E) * 2;

#pragma unroll
        for (int ks = 0; ks < 32; ks += 16) {
            uint32_t ah[2][4], al[2][4], bh[4][4], bl[4][4];
#pragma unroll
            for (int mt = 0; mt < 2; mt++) {
                uint32_t ao = cb + (uint32_t)((wm + mt * 16 + a_r) * LDT + ks + a_c) * 2;
                ldmatrix_x4(ah[mt][0], ah[mt][1], ah[mt][2], ah[mt][3], ao);
                ldmatrix_x4(al[mt][0], al[mt][1], al[mt][2], al[mt][3],
                            ao + (uint32_t)G_TILE * 2);
            }
#pragma unroll
            for (int ntp = 0; ntp < 4; ntp++) {
                uint32_t bo = cb + (uint32_t)(2 * G_TILE +
                               (wn + ntp * 16 + b_r) * LDT + ks + b_c) * 2;
                ldmatrix_x4(bh[ntp][0], bh[ntp][1], bh[ntp][2], bh[ntp][3], bo);
                ldmatrix_x4(bl[ntp][0], bl[ntp][1], bl[ntp][2], bl[ntp][3],
                            bo + (uint32_t)G_TILE * 2);
            }
#pragma unroll
            for (int mt = 0; mt < 2; mt++)
#pragma unroll
                for (int ntp = 0; ntp < 4; ntp++) {
                    mma_bf16(acc[mt][2 * ntp],     ah[mt], bh[ntp]);
                    mma_bf16(acc[mt][2 * ntp],     ah[mt], bl[ntp]);
                    mma_bf16(acc[mt][2 * ntp],     al[mt], bh[ntp]);
                    mma_bf16(acc[mt][2 * ntp + 1], ah[mt], bh[ntp] + 2);
                    mma_bf16(acc[mt][2 * ntp + 1], ah[mt], bl[ntp] + 2);
                    mma_bf16(acc[mt][2 * ntp + 1], al[mt], bh[ntp] + 2);
                }
        }
        __syncthreads();
    }

    // epilogue
#pragma unroll
    for (int nt = 0; nt < 8; nt++) {
        int col = bn + wn + nt * 8 + tig * 2;
        float b0 = bias[col];
        float b1 = bias[col + 1];
#pragma unroll
        for (int mt = 0; mt < 2; mt++) {
            int row = bm + wm + mt * 16 + g;
            float v00 = acc[mt][nt][0] + b0, v01 = acc[mt][nt][1] + b1;
            float v10 = acc[mt][nt][2] + b0, v11 = acc[mt][nt][3] + b1;
            if (SPLIT_OUT) {
                bf16 h00 = __float2bfloat16(v00), h01 = __float2bfloat16(v01);
                bf16 h10 = __float2bfloat16(v10), h11 = __float2bfloat16(v11);
                size_t i0 = (size_t)row * N + col;
                size_t i1 = (size_t)(row + 8) * N + col;
                *reinterpret_cast<uint32_t*>(&Chi[i0]) = pack_bf16(v00, v01);
                *reinterpret_cast<uint32_t*>(&Chi[i1]) = pack_bf16(v10, v11);
                *reinterpret_cast<uint32_t*>(&Clo[i0]) =
                    pack_bf16(v00 - __bfloat162float(h00), v01 - __bfloat162float(h01));
                *reinterpret_cast<uint32_t*>(&Clo[i1]) =
                    pack_bf16(v10 - __bfloat162float(h10), v11 - __bfloat162float(h11));
            } else {
                float2 w0 = {v00, v01}, w1 = {v10, v11};
                *reinterpret_cast<float2*>(&Cf[(size_t)row * N + col])       = w0;
                *reinterpret_cast<float2*>(&Cf[(size_t)(row + 8) * N + col]) = w1;
            }
        }
    }
}

// ---------------------------------------------------------------------------
// Tensor-core flash attention, all-bf16 dataflow.
// Inputs pre-split bf16 (from GEMM1 epilogue); outputs split bf16.
// CTA = (b,h,128-row Q tile), 8 warps x 16 rows. KV tiles 64 rows,
// cp.async double-buffered. V fragments via ldmatrix.trans (no transpose copy).
// ---------------------------------------------------------------------------
#define LDQ 136
#define QTILE 128
#define KTILE 64
#define A_SM_Q0 0
#define A_SM_Q1 (QTILE * LDQ)                 // 17408
#define A_SM_KV (2 * QTILE * LDQ)             // 34816
#define A_KV_TILE (KTILE * LDQ)               // 8704
#define A_KV_STAGE (4 * A_KV_TILE)            // 34816
#define ATTN_SMEM_ELEMS (A_SM_KV + 2 * A_KV_STAGE)
#define ATTN_SMEM_BYTES (ATTN_SMEM_ELEMS * 2) // 208896

__global__ __launch_bounds__(256, 1) void attn_tc_kernel(
    const bf16* __restrict__ qkvhi, const bf16* __restrict__ qkvlo,
    bf16* __restrict__ ahi, bf16* __restrict__ alo)
{
    extern __shared__ bf16 asmem[];
    const uint32_t sb = smem_u32(asmem);

    const int qt = blockIdx.x;
    const int h  = blockIdx.y;
    const int b  = blockIdx.z;

    const int tid  = threadIdx.x;
    const int lane = tid & 31;
    const int warp = tid >> 5;
    const int g    = lane >> 2;
    const int tig  = lane & 3;
    const int wr   = warp * 16;

    const int a_r  = lane & 15;
    const int a_c  = (lane >> 4) * 8;
    const int kb_r = ((lane >> 4) * 8) + (lane & 7);
    const int kb_c = ((lane >> 3) & 1) * 8;
    const int vb_r = (lane & 7) + ((lane >> 3) & 1) * 8;   // k dim (trans)
    const int vb_c = (lane >> 4) * 8;                       // n dim (trans)

    const float scale = 0.08838834764831845f;

    const size_t qoff = (size_t)(b * SEQ) * QKV_N + h * DH;
    const size_t koff = qoff + DM;
    const size_t voff = qoff + 2 * DM;

    auto issue_kv = [&](int j) {
        uint32_t stb = sb + (uint32_t)(A_SM_KV + (j & 1) * A_KV_STAGE) * 2;
#pragma unroll
        for (int jj = 0; jj < 16; jj++) {
            const int tile = jj >> 2;
            int q  = tid + (jj & 3) * 256;
            int r  = q >> 4;
            int ch = (q & 15) << 3;
            size_t grow = (size_t)(j * KTILE + r) * QKV_N + ch;
            const bf16* src =
                (tile == 0 ? qkvhi + koff : tile == 1 ? qkvlo + koff :
                 tile == 2 ? qkvhi + voff : qkvlo + voff) + grow;
            cp16(stb + (uint32_t)(tile * A_KV_TILE + r * LDQ + ch) * 2, src);
        }
    };

    // prologue: Q (both halves) + KV stage 0 as one group
    {
#pragma unroll
        for (int jj = 0; jj < 16; jj++) {
            const int arr = jj >> 3;
            int q  = tid + (jj & 7) * 256;
            int r  = q >> 4;
            int ch = (q & 15) << 3;
            const bf16* src = (arr ? qkvlo : qkvhi) + qoff
                              + (size_t)(qt * QTILE + r) * QKV_N + ch;
            cp16(sb + (uint32_t)((arr ? A_SM_Q1 : A_SM_Q0) + r * LDQ + ch) * 2, src);
        }
        issue_kv(0);
        CP_COMMIT();
    }

    float m0 = -INFINITY, m1 = -INFINITY, l0 = 0.0f, l1 = 0.0f;
    float o[16][4];
#pragma unroll
    for (int nt = 0; nt < 16; nt++)
#pragma unroll
        for (int i = 0; i < 4; i++) o[nt][i] = 0.0f;

    const int rowg  = qt * QTILE + wr + g;
    const int rowg8 = rowg + 8;
    const int njt   = 2 * qt + 2;

    const uint32_t qhi_a = sb + (uint32_t)(A_SM_Q0 + (wr + a_r) * LDQ + a_c) * 2;
    const uint32_t qlo_a = sb + (uint32_t)(A_SM_Q1 + (wr + a_r) * LDQ + a_c) * 2;

    for (int j = 0; j < njt; j++) {
        if (j + 1 < njt) issue_kv(j + 1);
        CP_COMMIT();
        CP_WAIT(1);
        __syncthreads();

        if (j * KTILE <= qt * QTILE + wr + 15) {
            const uint32_t kvb = sb + (uint32_t)(A_SM_KV + (j & 1) * A_KV_STAGE) * 2;
            const uint32_t khi_b = kvb + (uint32_t)(kb_r * LDQ + kb_c) * 2;
            const uint32_t klo_b = khi_b + (uint32_t)A_KV_TILE * 2;
            const uint32_t vhi_b = kvb + (uint32_t)(2 * A_KV_TILE + vb_r * LDQ + vb_c) * 2;
            const uint32_t vlo_b = vhi_b + (uint32_t)A_KV_TILE * 2;

            // ---- S = Q @ K^T ----
            float s[8][4];
#pragma unroll
            for (int nt = 0; nt < 8; nt++)
#pragma unroll
                for (int i = 0; i < 4; i++) s[nt][i] = 0.0f;

#pragma unroll
            for (int ks = 0; ks < 8; ks++) {
                uint32_t ah[4], al[4];
                ldmatrix_x4(ah[0], ah[1], ah[2], ah[3], qhi_a + ks * 32);
                ldmatrix_x4(al[0], al[1], al[2], al[3], qlo_a + ks * 32);
#pragma unroll
                for (int ntp = 0; ntp < 4; ntp++) {
                    uint32_t bh[4], bl[4];
                    ldmatrix_x4(bh[0], bh[1], bh[2], bh[3],
                                khi_b + (uint32_t)(ntp * 16 * LDQ + ks * 16) * 2);
                    ldmatrix_x4(bl[0], bl[1], bl[2], bl[3],
                                klo_b + (uint32_t)(ntp * 16 * LDQ + ks * 16) * 2);
                    mma_bf16(s[2 * ntp],     ah, bh);
                    mma_bf16(s[2 * ntp],     ah, bl);
                    mma_bf16(s[2 * ntp],     al, bh);
                    mma_bf16(s[2 * ntp + 1], ah, bh + 2);
                    mma_bf16(s[2 * ntp + 1], ah, bl + 2);
                    mma_bf16(s[2 * ntp + 1], al, bh + 2);
                }
            }

            // ---- scale + causal mask ----
#pragma unroll
            for (int nt = 0; nt < 8; nt++)
#pragma unroll
                for (int i = 0; i < 4; i++) s[nt][i] *= scale;

            const int jc = j * KTILE;
            if (jc + KTILE - 1 > rowg) {
#pragma unroll
                for (int nt = 0; nt < 8; nt++) {
                    int c0 = jc + nt * 8 + tig * 2;
                    if (c0     > rowg) s[nt][0] = -1e30f;
                    if (c0 + 1 > rowg) s[nt][1] = -1e30f;
                }
            }
            if (jc + KTILE - 1 > rowg8) {
#pragma unroll
                for (int nt = 0; nt < 8; nt++) {
                    int c0 = jc + nt * 8 + tig * 2;
                    if (c0     > rowg8) s[nt][2] = -1e30f;
                    if (c0 + 1 > rowg8) s[nt][3] = -1e30f;
                }
            }

            // ---- online softmax ----
            float mt0 = -1e30f, mt1 = -1e30f;
#pragma unroll
            for (int nt = 0; nt < 8; nt++) {
                mt0 = fmaxf(mt0, fmaxf(s[nt][0], s[nt][1]));
                mt1 = fmaxf(mt1, fmaxf(s[nt][2], s[nt][3]));
            }
            mt0 = fmaxf(mt0, __shfl_xor_sync(0xffffffffu, mt0, 1));
            mt0 = fmaxf(mt0, __shfl_xor_sync(0xffffffffu, mt0, 2));
            mt1 = fmaxf(mt1, __shfl_xor_sync(0xffffffffu, mt1, 1));
            mt1 = fmaxf(mt1, __shfl_xor_sync(0xffffffffu, mt1, 2));

            float mn0 = fmaxf(m0, mt0);
            float mn1 = fmaxf(m1, mt1);
            float al0 = __expf(m0 - mn0);
            float al1 = __expf(m1 - mn1);
            m0 = mn0; m1 = mn1;

            float rs0 = 0.0f, rs1 = 0.0f;
#pragma unroll
            for (int nt = 0; nt < 8; nt++) {
                s[nt][0] = __expf(s[nt][0] - mn0); rs0 += s[nt][0];
                s[nt][1] = __expf(s[nt][1] - mn0); rs0 += s[nt][1];
                s[nt][2] = __expf(s[nt][2] - mn1); rs1 += s[nt][2];
                s[nt][3] = __expf(s[nt][3] - mn1); rs1 += s[nt][3];
            }
            rs0 += __shfl_xor_sync(0xffffffffu, rs0, 1);
            rs0 += __shfl_xor_sync(0xffffffffu, rs0, 2);
            rs1 += __shfl_xor_sync(0xffffffffu, rs1, 1);
            rs1 += __shfl_xor_sync(0xffffffffu, rs1, 2);

            l0 = l0 * al0 + rs0;
            l1 = l1 * al1 + rs1;
#pragma unroll
            for (int nt = 0; nt < 16; nt++) {
                o[nt][0] *= al0; o[nt][1] *= al0;
                o[nt][2] *= al1; o[nt][3] *= al1;
            }

            // ---- O += P @ V ----
#pragma unroll
            for (int ks = 0; ks < 4; ks++) {
                uint32_t ph[4], pl[4];
#pragma unroll
                for (int half = 0; half < 2; half++) {
                    float p0 = s[2 * ks + half][0];
                    float p1 = s[2 * ks + half][1];
                    float p2 = s[2 * ks + half][2];
                    float p3 = s[2 * ks + half][3];
                    bf16 h0 = __float2bfloat16(p0), h1 = __float2bfloat16(p1);
                    bf16 h2 = __float2bfloat16(p2), h3 = __float2bfloat16(p3);
                    ph[0 + 2 * half] = pack_bf16(p0, p1);
                    ph[1 + 2 * half] = pack_bf16(p2, p3);
                    pl[0 + 2 * half] = pack_bf16(p0 - __bfloat162float(h0),
                                                 p1 - __bfloat162float(h1));
                    pl[1 + 2 * half] = pack_bf16(p2 - __bfloat162float(h2),
                                                 p3 - __bfloat162float(h3));
                }
#pragma unroll
                for (int ntp = 0; ntp < 8; ntp++) {
                    uint32_t bh[4], bl[4];
                    ldmatrix_x4_trans(bh[0], bh[1], bh[2], bh[3],
                                      vhi_b + (uint32_t)(ks * 16 * LDQ + ntp * 16) * 2);
                    ldmatrix_x4_trans(bl[0], bl[1], bl[2], bl[3],
                                      vlo_b + (uint32_t)(ks * 16 * LDQ + ntp * 16) * 2);
                    mma_bf16(o[2 * ntp],     ph, bh);
                    mma_bf16(o[2 * ntp],     ph, bl);
                    mma_bf16(o[2 * ntp],     pl, bh);
                    mma_bf16(o[2 * ntp + 1], ph, bh + 2);
                    mma_bf16(o[2 * ntp + 1], ph, bl + 2);
                    mma_bf16(o[2 * ntp + 1], pl, bh + 2);
                }
            }
        }
        __syncthreads();
    }

    // ---- normalize + split store ----
    const float inv0 = 1.0f / l0;
    const float inv1 = 1.0f / l1;
#pragma unroll
    for (int nt = 0; nt < 16; nt++) {
        int col = h * DH + nt * 8 + tig * 2;
        size_t i0 = (size_t)(b * SEQ + rowg)  * DM + col;
        size_t i1 = (size_t)(b * SEQ + rowg8) * DM + col;
        float v0 = o[nt][0] * inv0, v1 = o[nt][1] * inv0;
        float v2 = o[nt][2] * inv1, v3 = o[nt][3] * inv1;
        bf16 h0 = __float2bfloat16(v0), h1 = __float2bfloat16(v1);
        bf16 h2 = __float2bfloat16(v2), h3 = __float2bfloat16(v3);
        *reinterpret_cast<uint32_t*>(&ahi[i0]) = pack_bf16(v0, v1);
        *reinterpret_cast<uint32_t*>(&ahi[i1]) = pack_bf16(v2, v3);
        *reinterpret_cast<uint32_t*>(&alo[i0]) =
            pack_bf16(v0 - __bfloat162float(h0), v1 - __bfloat162float(h1));
        *reinterpret_cast<uint32_t*>(&alo[i1]) =
            pack_bf16(v2 - __bfloat162float(h2), v3 - __bfloat162float(h3));
    }
}

// ---------------------------------------------------------------------------
extern "C" void kernel_launch(void* const* d_in, const int* in_sizes, int n_in,
                              void* d_out, int out_size)
{
    const float* x     = (const float*)d_in[0];
    const float* w_qkv = (const float*)d_in[1];
    const float* b_qkv = (const float*)d_in[2];
    const float* w_out = (const float*)d_in[3];
    const float* b_out = (const float*)d_in[4];
    float* out = (float*)d_out;

    bf16 *xhi, *xlo, *qh, *ql, *ahi, *alo, *wqh, *wql, *woh, *wol;
    cudaGetSymbolAddress((void**)&xhi, g_xhi);
    cudaGetSymbolAddress((void**)&xlo, g_xlo);
    cudaGetSymbolAddress((void**)&qh,  g_qkvhi);
    cudaGetSymbolAddress((void**)&ql,  g_qkvlo);
    cudaGetSymbolAddress((void**)&ahi, g_ahi);
    cudaGetSymbolAddress((void**)&alo, g_alo);
    cudaGetSymbolAddress((void**)&wqh, g_wqt_hi);
    cudaGetSymbolAddress((void**)&wql, g_wqt_lo);
    cudaGetSymbolAddress((void**)&woh, g_wot_hi);
    cudaGetSymbolAddress((void**)&wol, g_wot_lo);

    cudaFuncSetAttribute(attn_tc_kernel,
                         cudaFuncAttributeMaxDynamicSharedMemorySize,
                         ATTN_SMEM_BYTES);
    cudaFuncSetAttribute(gemm_tc_kernel<true>,
                         cudaFuncAttributeMaxDynamicSharedMemorySize,
                         GEMM_SMEM_BYTES);
    cudaFuncSetAttribute(gemm_tc_kernel<false>,
                         cudaFuncAttributeMaxDynamicSharedMemorySize,
                         GEMM_SMEM_BYTES);

    // 0a) split x -> bf16 hi/lo
    {
        int n4 = (MROWS * DM) / 4;
        split_kernel<<<n4 / 256, 256>>>((const float4*)x,
                                        (__nv_bfloat162*)xhi, (__nv_bfloat162*)xlo, n4);
    }
    // 0b) transpose+split weights
    {
        dim3 b32(32, 8);
        dim3 gq(QKV_N / 32, DM / 32);
        transpose_split_kernel<<<gq, b32>>>(w_qkv, wqh, wql, DM, QKV_N);
        dim3 go(DM / 32, DM / 32);
        transpose_split_kernel<<<go, b32>>>(w_out, woh, wol, DM, DM);
    }
    // 1) QKV projection -> split bf16 output
    {
        dim3 g1(QKV_N / 128, MROWS / 128);
        gemm_tc_kernel<true><<<g1, 256, GEMM_SMEM_BYTES>>>(
            xhi, xlo, wqh, wql, b_qkv, nullptr, qh, ql, MROWS, QKV_N, DM);
    }
    // 2) Attention (all-bf16 dataflow) -> split bf16 output
    {
        dim3 g2(SEQ / QTILE, NH, BATCH);
        attn_tc_kernel<<<g2, 256, ATTN_SMEM_BYTES>>>(qh, ql, ahi, alo);
    }
    // 3) Output projection -> fp32
    {
        dim3 g3(DM / 128, MROWS / 128);
        gemm_tc_kernel<false><<<g3, 256, GEMM_SMEM_BYTES>>>(
            ahi, alo, woh, wol, b_out, out, nullptr, nullptr, MROWS, DM, DM);
    }
}

// round 5
// speedup vs baseline: 3.3962x; 1.2401x over previous
#include <cuda_runtime.h>
#include <cuda_bf16.h>
#include <cstdint>
#include <math.h>

typedef __nv_bfloat16 bf16;

// Problem constants
#define BATCH   4
#define SEQ     2048
#define DM      2048
#define NH      16
#define DH      128
#define MROWS   (BATCH * SEQ)   // 8192
#define QKV_N   (3 * DM)        // 6144

// ---------------------------------------------------------------------------
// Device scratch (allocation-free per harness rules)
// ---------------------------------------------------------------------------
__device__ bf16 g_xhi[(size_t)MROWS * DM];
__device__ bf16 g_xlo[(size_t)MROWS * DM];
__device__ bf16 g_qkvhi[(size_t)MROWS * QKV_N];     // split qkv (GEMM1 out)
__device__ bf16 g_qkvlo[(size_t)MROWS * QKV_N];
__device__ bf16 g_ahi[(size_t)MROWS * DM];          // split attn out
__device__ bf16 g_alo[(size_t)MROWS * DM];
__device__ bf16 g_wqt_hi[(size_t)QKV_N * DM];       // w_qkv^T  [N,K]
__device__ bf16 g_wqt_lo[(size_t)QKV_N * DM];
__device__ bf16 g_wot_hi[(size_t)DM * DM];          // w_out^T  [N,K]
__device__ bf16 g_wot_lo[(size_t)DM * DM];

// ---------------------------------------------------------------------------
// Helpers
// ---------------------------------------------------------------------------
__device__ __forceinline__ uint32_t smem_u32(const void* p) {
    uint32_t a;
    asm("{ .reg .u64 t; cvta.to.shared.u64 t, %1; cvt.u32.u64 %0, t; }"
        : "=r"(a) : "l"(p));
    return a;
}

__device__ __forceinline__ uint32_t pack_bf16(float a, float b) {
    __nv_bfloat162 t = __floats2bfloat162_rn(a, b);
    return *reinterpret_cast<uint32_t*>(&t);
}

__device__ __forceinline__ void cp16(uint32_t dst, const void* src) {
    asm volatile("cp.async.cg.shared.global [%0], [%1], 16;\n"
                 :: "r"(dst), "l"(src));
}
#define CP_COMMIT() asm volatile("cp.async.commit_group;\n")
#define CP_WAIT(N)  asm volatile("cp.async.wait_group %0;\n" :: "n"(N))

__device__ __forceinline__ void ldmatrix_x4(uint32_t& r0, uint32_t& r1,
                                            uint32_t& r2, uint32_t& r3,
                                            uint32_t addr) {
    asm volatile("ldmatrix.sync.aligned.m8n8.x4.shared.b16 {%0,%1,%2,%3}, [%4];\n"
                 : "=r"(r0), "=r"(r1), "=r"(r2), "=r"(r3) : "r"(addr));
}
__device__ __forceinline__ void ldmatrix_x4_trans(uint32_t& r0, uint32_t& r1,
                                                  uint32_t& r2, uint32_t& r3,
                                                  uint32_t addr) {
    asm volatile("ldmatrix.sync.aligned.m8n8.x4.trans.shared.b16 {%0,%1,%2,%3}, [%4];\n"
                 : "=r"(r0), "=r"(r1), "=r"(r2), "=r"(r3) : "r"(addr));
}

__device__ __forceinline__ void mma_bf16(float* d, const uint32_t* a, const uint32_t* b)
{
    asm volatile(
        "mma.sync.aligned.m16n8k16.row.col.f32.bf16.bf16.f32 "
        "{%0,%1,%2,%3}, {%4,%5,%6,%7}, {%8,%9}, {%0,%1,%2,%3};\n"
        : "+f"(d[0]), "+f"(d[1]), "+f"(d[2]), "+f"(d[3])
        : "r"(a[0]), "r"(a[1]), "r"(a[2]), "r"(a[3]),
          "r"(b[0]), "r"(b[1]));
}

// ---------------------------------------------------------------------------
// Elementwise fp32 -> (bf16 hi, bf16 lo) split
// ---------------------------------------------------------------------------
__global__ void split_kernel(const float4* __restrict__ src,
                             __nv_bfloat162* __restrict__ hi,
                             __nv_bfloat162* __restrict__ lo,
                             int n4)
{
    int idx = blockIdx.x * blockDim.x + threadIdx.x;
    if (idx >= n4) return;
    float4 v = src[idx];
    bf16 hx = __float2bfloat16(v.x);
    bf16 hy = __float2bfloat16(v.y);
    bf16 hz = __float2bfloat16(v.z);
    bf16 hw = __float2bfloat16(v.w);
    bf16 lx = __float2bfloat16(v.x - __bfloat162float(hx));
    bf16 ly = __float2bfloat16(v.y - __bfloat162float(hy));
    bf16 lz = __float2bfloat16(v.z - __bfloat162float(hz));
    bf16 lw = __float2bfloat16(v.w - __bfloat162float(hw));
    hi[idx * 2 + 0] = __nv_bfloat162(hx, hy);
    hi[idx * 2 + 1] = __nv_bfloat162(hz, hw);
    lo[idx * 2 + 0] = __nv_bfloat162(lx, ly);
    lo[idx * 2 + 1] = __nv_bfloat162(lz, lw);
}

// ---------------------------------------------------------------------------
// Transpose + split: src [K,N] fp32 -> hi/lo [N,K] bf16
// ---------------------------------------------------------------------------
__global__ void transpose_split_kernel(const float* __restrict__ src,
                                       bf16* __restrict__ hi,
                                       bf16* __restrict__ lo,
                                       int K, int N)
{
    __shared__ float t[32][33];
    int nb = blockIdx.x * 32, kb = blockIdx.y * 32;
    int tx = threadIdx.x, ty = threadIdx.y;
#pragma unroll
    for (int i = 0; i < 4; i++)
        t[ty + i * 8][tx] = src[(size_t)(kb + ty + i * 8) * N + nb + tx];
    __syncthreads();
#pragma unroll
    for (int i = 0; i < 4; i++) {
        float v = t[tx][ty + i * 8];
        size_t o = (size_t)(nb + ty + i * 8) * K + kb + tx;
        bf16 h = __float2bfloat16(v);
        hi[o] = h;
        lo[o] = __float2bfloat16(v - __bfloat162float(h));
    }
}

// ---------------------------------------------------------------------------
// Split-bf16 tensor-core GEMM, 2-stage cp.async pipeline, 2 CTAs/SM.
//   C[M,N] = (Ah+Al)[M,K] @ (Bh+Bl)^T (B stored [N,K]) + bias[N]
// Block 128x128x32, 8 warps (warp tile 32x64), m16n8k16, 3 MMAs per pair.
// SPLIT_OUT: emit bf16 hi/lo split instead of fp32.
// ---------------------------------------------------------------------------
#define LDT 40
#define G_TILE (128 * LDT)               // elems per operand tile (5120)
#define G_STAGE_E (4 * G_TILE)           // elems per stage (20480)
#define G_STAGES 2
#define GEMM_SMEM_BYTES (G_STAGES * G_STAGE_E * 2)   // 81920 -> 2 CTAs/SM

template<bool SPLIT_OUT>
__global__ __launch_bounds__(256, 2) void gemm_tc_kernel(
    const bf16* __restrict__ Ah, const bf16* __restrict__ Al,
    const bf16* __restrict__ Bh, const bf16* __restrict__ Bl,
    const float* __restrict__ bias,
    float* __restrict__ Cf, bf16* __restrict__ Chi, bf16* __restrict__ Clo,
    int M, int N, int K)
{
    extern __shared__ bf16 gsm[];
    const uint32_t sb = smem_u32(gsm);

    const int tid  = threadIdx.x;
    const int lane = tid & 31;
    const int warp = tid >> 5;
    const int bm = blockIdx.y * 128;
    const int bn = blockIdx.x * 128;
    const int wm = (warp >> 1) * 32;
    const int wn = (warp & 1) * 64;
    const int g   = lane >> 2;
    const int tig = lane & 3;

    const int a_r = lane & 15;
    const int a_c = (lane >> 4) * 8;
    const int b_r = ((lane >> 4) * 8) + (lane & 7);
    const int b_c = ((lane >> 3) & 1) * 8;

    const bf16* gsrc0 = Ah + (size_t)bm * K;
    const bf16* gsrc1 = Al + (size_t)bm * K;
    const bf16* gsrc2 = Bh + (size_t)bn * K;
    const bf16* gsrc3 = Bl + (size_t)bn * K;

    const int nk = K >> 5;

    auto issue = [&](int t) {
        if (t < nk) {
            int k0 = t << 5;
            uint32_t stb = sb + (uint32_t)((t & (G_STAGES - 1)) * G_STAGE_E) * 2;
#pragma unroll
            for (int jj = 0; jj < 8; jj++) {
                const int tile = jj >> 1;
                int q  = tid + (jj & 1) * 256;
                int r  = q >> 2;
                int ch = (q & 3) << 3;
                const bf16* src =
                    (tile == 0 ? gsrc0 : tile == 1 ? gsrc1 : tile == 2 ? gsrc2 : gsrc3)
                    + (size_t)r * K + k0 + ch;
                cp16(stb + (uint32_t)(tile * G_TILE + r * LDT + ch) * 2, src);
            }
        }
        CP_COMMIT();
    };

    issue(0);

    float acc[2][8][4];
#pragma unroll
    for (int mt = 0; mt < 2; mt++)
#pragma unroll
        for (int nt = 0; nt < 8; nt++)
#pragma unroll
            for (int i = 0; i < 4; i++) acc[mt][nt][i] = 0.0f;

    for (int t = 0; t < nk; t++) {
        // prefetch next stage into the buffer freed at end of previous iter
        issue(t + 1);
        CP_WAIT(1);
        __syncthreads();
        const uint32_t cb = sb + (uint32_t)((t & (G_STAGES - 1)) * G_STAGE_E) * 2;

#pragma unroll
        for (int ks = 0; ks < 32; ks += 16) {
            uint32_t ah[2][4], al[2][4], bh[4][4], bl[4][4];
#pragma unroll
            for (int mt = 0; mt < 2; mt++) {
                uint32_t ao = cb + (uint32_t)((wm + mt * 16 + a_r) * LDT + ks + a_c) * 2;
                ldmatrix_x4(ah[mt][0], ah[mt][1], ah[mt][2], ah[mt][3], ao);
                ldmatrix_x4(al[mt][0], al[mt][1], al[mt][2], al[mt][3],
                            ao + (uint32_t)G_TILE * 2);
            }
#pragma unroll
            for (int ntp = 0; ntp < 4; ntp++) {
                uint32_t bo = cb + (uint32_t)(2 * G_TILE +
                               (wn + ntp * 16 + b_r) * LDT + ks + b_c) * 2;
                ldmatrix_x4(bh[ntp][0], bh[ntp][1], bh[ntp][2], bh[ntp][3], bo);
                ldmatrix_x4(bl[ntp][0], bl[ntp][1], bl[ntp][2], bl[ntp][3],
                            bo + (uint32_t)G_TILE * 2);
            }
#pragma unroll
            for (int mt = 0; mt < 2; mt++)
#pragma unroll
                for (int ntp = 0; ntp < 4; ntp++) {
                    mma_bf16(acc[mt][2 * ntp],     ah[mt], bh[ntp]);
                    mma_bf16(acc[mt][2 * ntp],     ah[mt], bl[ntp]);
                    mma_bf16(acc[mt][2 * ntp],     al[mt], bh[ntp]);
                    mma_bf16(acc[mt][2 * ntp + 1], ah[mt], bh[ntp] + 2);
                    mma_bf16(acc[mt][2 * ntp + 1], ah[mt], bl[ntp] + 2);
                    mma_bf16(acc[mt][2 * ntp + 1], al[mt], bh[ntp] + 2);
                }
        }
        __syncthreads();
    }

    // epilogue
#pragma unroll
    for (int nt = 0; nt < 8; nt++) {
        int col = bn + wn + nt * 8 + tig * 2;
        float b0 = bias[col];
        float b1 = bias[col + 1];
#pragma unroll
        for (int mt = 0; mt < 2; mt++) {
            int row = bm + wm + mt * 16 + g;
            float v00 = acc[mt][nt][0] + b0, v01 = acc[mt][nt][1] + b1;
            float v10 = acc[mt][nt][2] + b0, v11 = acc[mt][nt][3] + b1;
            if (SPLIT_OUT) {
                bf16 h00 = __float2bfloat16(v00), h01 = __float2bfloat16(v01);
                bf16 h10 = __float2bfloat16(v10), h11 = __float2bfloat16(v11);
                size_t i0 = (size_t)row * N + col;
                size_t i1 = (size_t)(row + 8) * N + col;
                *reinterpret_cast<uint32_t*>(&Chi[i0]) = pack_bf16(v00, v01);
                *reinterpret_cast<uint32_t*>(&Chi[i1]) = pack_bf16(v10, v11);
                *reinterpret_cast<uint32_t*>(&Clo[i0]) =
                    pack_bf16(v00 - __bfloat162float(h00), v01 - __bfloat162float(h01));
                *reinterpret_cast<uint32_t*>(&Clo[i1]) =
                    pack_bf16(v10 - __bfloat162float(h10), v11 - __bfloat162float(h11));
            } else {
                float2 w0 = {v00, v01}, w1 = {v10, v11};
                *reinterpret_cast<float2*>(&Cf[(size_t)row * N + col])       = w0;
                *reinterpret_cast<float2*>(&Cf[(size_t)(row + 8) * N + col]) = w1;
            }
        }
    }
}

// ---------------------------------------------------------------------------
// Tensor-core flash attention, all-bf16 dataflow (unchanged from R4).
// ---------------------------------------------------------------------------
#define LDQ 136
#define QTILE 128
#define KTILE 64
#define A_SM_Q0 0
#define A_SM_Q1 (QTILE * LDQ)                 // 17408
#define A_SM_KV (2 * QTILE * LDQ)             // 34816
#define A_KV_TILE (KTILE * LDQ)               // 8704
#define A_KV_STAGE (4 * A_KV_TILE)            // 34816
#define ATTN_SMEM_ELEMS (A_SM_KV + 2 * A_KV_STAGE)
#define ATTN_SMEM_BYTES (ATTN_SMEM_ELEMS * 2) // 208896

__global__ __launch_bounds__(256, 1) void attn_tc_kernel(
    const bf16* __restrict__ qkvhi, const bf16* __restrict__ qkvlo,
    bf16* __restrict__ ahi, bf16* __restrict__ alo)
{
    extern __shared__ bf16 asmem[];
    const uint32_t sb = smem_u32(asmem);

    const int qt = blockIdx.x;
    const int h  = blockIdx.y;
    const int b  = blockIdx.z;

    const int tid  = threadIdx.x;
    const int lane = tid & 31;
    const int warp = tid >> 5;
    const int g    = lane >> 2;
    const int tig  = lane & 3;
    const int wr   = warp * 16;

    const int a_r  = lane & 15;
    const int a_c  = (lane >> 4) * 8;
    const int kb_r = ((lane >> 4) * 8) + (lane & 7);
    const int kb_c = ((lane >> 3) & 1) * 8;
    const int vb_r = (lane & 7) + ((lane >> 3) & 1) * 8;   // k dim (trans)
    const int vb_c = (lane >> 4) * 8;                       // n dim (trans)

    const float scale = 0.08838834764831845f;

    const size_t qoff = (size_t)(b * SEQ) * QKV_N + h * DH;
    const size_t koff = qoff + DM;
    const size_t voff = qoff + 2 * DM;

    auto issue_kv = [&](int j) {
        uint32_t stb = sb + (uint32_t)(A_SM_KV + (j & 1) * A_KV_STAGE) * 2;
#pragma unroll
        for (int jj = 0; jj < 16; jj++) {
            const int tile = jj >> 2;
            int q  = tid + (jj & 3) * 256;
            int r  = q >> 4;
            int ch = (q & 15) << 3;
            size_t grow = (size_t)(j * KTILE + r) * QKV_N + ch;
            const bf16* src =
                (tile == 0 ? qkvhi + koff : tile == 1 ? qkvlo + koff :
                 tile == 2 ? qkvhi + voff : qkvlo + voff) + grow;
            cp16(stb + (uint32_t)(tile * A_KV_TILE + r * LDQ + ch) * 2, src);
        }
    };

    // prologue: Q (both halves) + KV stage 0 as one group
    {
#pragma unroll
        for (int jj = 0; jj < 16; jj++) {
            const int arr = jj >> 3;
            int q  = tid + (jj & 7) * 256;
            int r  = q >> 4;
            int ch = (q & 15) << 3;
            const bf16* src = (arr ? qkvlo : qkvhi) + qoff
                              + (size_t)(qt * QTILE + r) * QKV_N + ch;
            cp16(sb + (uint32_t)((arr ? A_SM_Q1 : A_SM_Q0) + r * LDQ + ch) * 2, src);
        }
        issue_kv(0);
        CP_COMMIT();
    }

    float m0 = -INFINITY, m1 = -INFINITY, l0 = 0.0f, l1 = 0.0f;
    float o[16][4];
#pragma unroll
    for (int nt = 0; nt < 16; nt++)
#pragma unroll
        for (int i = 0; i < 4; i++) o[nt][i] = 0.0f;

    const int rowg  = qt * QTILE + wr + g;
    const int rowg8 = rowg + 8;
    const int njt   = 2 * qt + 2;

    const uint32_t qhi_a = sb + (uint32_t)(A_SM_Q0 + (wr + a_r) * LDQ + a_c) * 2;
    const uint32_t qlo_a = sb + (uint32_t)(A_SM_Q1 + (wr + a_r) * LDQ + a_c) * 2;

    for (int j = 0; j < njt; j++) {
        if (j + 1 < njt) issue_kv(j + 1);
        CP_COMMIT();
        CP_WAIT(1);
        __syncthreads();

        if (j * KTILE <= qt * QTILE + wr + 15) {
            const uint32_t kvb = sb + (uint32_t)(A_SM_KV + (j & 1) * A_KV_STAGE) * 2;
            const uint32_t khi_b = kvb + (uint32_t)(kb_r * LDQ + kb_c) * 2;
            const uint32_t klo_b = khi_b + (uint32_t)A_KV_TILE * 2;
            const uint32_t vhi_b = kvb + (uint32_t)(2 * A_KV_TILE + vb_r * LDQ + vb_c) * 2;
            const uint32_t vlo_b = vhi_b + (uint32_t)A_KV_TILE * 2;

            // ---- S = Q @ K^T ----
            float s[8][4];
#pragma unroll
            for (int nt = 0; nt < 8; nt++)
#pragma unroll
                for (int i = 0; i < 4; i++) s[nt][i] = 0.0f;

#pragma unroll
            for (int ks = 0; ks < 8; ks++) {
                uint32_t ah[4], al[4];
                ldmatrix_x4(ah[0], ah[1], ah[2], ah[3], qhi_a + ks * 32);
                ldmatrix_x4(al[0], al[1], al[2], al[3], qlo_a + ks * 32);
#pragma unroll
                for (int ntp = 0; ntp < 4; ntp++) {
                    uint32_t bh[4], bl[4];
                    ldmatrix_x4(bh[0], bh[1], bh[2], bh[3],
                                khi_b + (uint32_t)(ntp * 16 * LDQ + ks * 16) * 2);
                    ldmatrix_x4(bl[0], bl[1], bl[2], bl[3],
                                klo_b + (uint32_t)(ntp * 16 * LDQ + ks * 16) * 2);
                    mma_bf16(s[2 * ntp],     ah, bh);
                    mma_bf16(s[2 * ntp],     ah, bl);
                    mma_bf16(s[2 * ntp],     al, bh);
                    mma_bf16(s[2 * ntp + 1], ah, bh + 2);
                    mma_bf16(s[2 * ntp + 1], ah, bl + 2);
                    mma_bf16(s[2 * ntp + 1], al, bh + 2);
                }
            }

            // ---- scale + causal mask ----
#pragma unroll
            for (int nt = 0; nt < 8; nt++)
#pragma unroll
                for (int i = 0; i < 4; i++) s[nt][i] *= scale;

            const int jc = j * KTILE;
            if (jc + KTILE - 1 > rowg) {
#pragma unroll
                for (int nt = 0; nt < 8; nt++) {
                    int c0 = jc + nt * 8 + tig * 2;
                    if (c0     > rowg) s[nt][0] = -1e30f;
                    if (c0 + 1 > rowg) s[nt][1] = -1e30f;
                }
            }
            if (jc + KTILE - 1 > rowg8) {
#pragma unroll
                for (int nt = 0; nt < 8; nt++) {
                    int c0 = jc + nt * 8 + tig * 2;
                    if (c0     > rowg8) s[nt][2] = -1e30f;
                    if (c0 + 1 > rowg8) s[nt][3] = -1e30f;
                }
            }

            // ---- online softmax ----
            float mt0 = -1e30f, mt1 = -1e30f;
#pragma unroll
            for (int nt = 0; nt < 8; nt++) {
                mt0 = fmaxf(mt0, fmaxf(s[nt][0], s[nt][1]));
                mt1 = fmaxf(mt1, fmaxf(s[nt][2], s[nt][3]));
            }
            mt0 = fmaxf(mt0, __shfl_xor_sync(0xffffffffu, mt0, 1));
            mt0 = fmaxf(mt0, __shfl_xor_sync(0xffffffffu, mt0, 2));
            mt1 = fmaxf(mt1, __shfl_xor_sync(0xffffffffu, mt1, 1));
            mt1 = fmaxf(mt1, __shfl_xor_sync(0xffffffffu, mt1, 2));

            float mn0 = fmaxf(m0, mt0);
            float mn1 = fmaxf(m1, mt1);
            float al0 = __expf(m0 - mn0);
            float al1 = __expf(m1 - mn1);
            m0 = mn0; m1 = mn1;

            float rs0 = 0.0f, rs1 = 0.0f;
#pragma unroll
            for (int nt = 0; nt < 8; nt++) {
                s[nt][0] = __expf(s[nt][0] - mn0); rs0 += s[nt][0];
                s[nt][1] = __expf(s[nt][1] - mn0); rs0 += s[nt][1];
                s[nt][2] = __expf(s[nt][2] - mn1); rs1 += s[nt][2];
                s[nt][3] = __expf(s[nt][3] - mn1); rs1 += s[nt][3];
            }
            rs0 += __shfl_xor_sync(0xffffffffu, rs0, 1);
            rs0 += __shfl_xor_sync(0xffffffffu, rs0, 2);
            rs1 += __shfl_xor_sync(0xffffffffu, rs1, 1);
            rs1 += __shfl_xor_sync(0xffffffffu, rs1, 2);

            l0 = l0 * al0 + rs0;
            l1 = l1 * al1 + rs1;
#pragma unroll
            for (int nt = 0; nt < 16; nt++) {
                o[nt][0] *= al0; o[nt][1] *= al0;
                o[nt][2] *= al1; o[nt][3] *= al1;
            }

            // ---- O += P @ V ----
#pragma unroll
            for (int ks = 0; ks < 4; ks++) {
                uint32_t ph[4], pl[4];
#pragma unroll
                for (int half = 0; half < 2; half++) {
                    float p0 = s[2 * ks + half][0];
                    float p1 = s[2 * ks + half][1];
                    float p2 = s[2 * ks + half][2];
                    float p3 = s[2 * ks + half][3];
                    bf16 h0 = __float2bfloat16(p0), h1 = __float2bfloat16(p1);
                    bf16 h2 = __float2bfloat16(p2), h3 = __float2bfloat16(p3);
                    ph[0 + 2 * half] = pack_bf16(p0, p1);
                    ph[1 + 2 * half] = pack_bf16(p2, p3);
                    pl[0 + 2 * half] = pack_bf16(p0 - __bfloat162float(h0),
                                                 p1 - __bfloat162float(h1));
                    pl[1 + 2 * half] = pack_bf16(p2 - __bfloat162float(h2),
                                                 p3 - __bfloat162float(h3));
                }
#pragma unroll
                for (int ntp = 0; ntp < 8; ntp++) {
                    uint32_t bh[4], bl[4];
                    ldmatrix_x4_trans(bh[0], bh[1], bh[2], bh[3],
                                      vhi_b + (uint32_t)(ks * 16 * LDQ + ntp * 16) * 2);
                    ldmatrix_x4_trans(bl[0], bl[1], bl[2], bl[3],
                                      vlo_b + (uint32_t)(ks * 16 * LDQ + ntp * 16) * 2);
                    mma_bf16(o[2 * ntp],     ph, bh);
                    mma_bf16(o[2 * ntp],     ph, bl);
                    mma_bf16(o[2 * ntp],     pl, bh);
                    mma_bf16(o[2 * ntp + 1], ph, bh + 2);
                    mma_bf16(o[2 * ntp + 1], ph, bl + 2);
                    mma_bf16(o[2 * ntp + 1], pl, bh + 2);
                }
            }
        }
        __syncthreads();
    }

    // ---- normalize + split store ----
    const float inv0 = 1.0f / l0;
    const float inv1 = 1.0f / l1;
#pragma unroll
    for (int nt = 0; nt < 16; nt++) {
        int col = h * DH + nt * 8 + tig * 2;
        size_t i0 = (size_t)(b * SEQ + rowg)  * DM + col;
        size_t i1 = (size_t)(b * SEQ + rowg8) * DM + col;
        float v0 = o[nt][0] * inv0, v1 = o[nt][1] * inv0;
        float v2 = o[nt][2] * inv1, v3 = o[nt][3] * inv1;
        bf16 h0 = __float2bfloat16(v0), h1 = __float2bfloat16(v1);
        bf16 h2 = __float2bfloat16(v2), h3 = __float2bfloat16(v3);
        *reinterpret_cast<uint32_t*>(&ahi[i0]) = pack_bf16(v0, v1);
        *reinterpret_cast<uint32_t*>(&ahi[i1]) = pack_bf16(v2, v3);
        *reinterpret_cast<uint32_t*>(&alo[i0]) =
            pack_bf16(v0 - __bfloat162float(h0), v1 - __bfloat162float(h1));
        *reinterpret_cast<uint32_t*>(&alo[i1]) =
            pack_bf16(v2 - __bfloat162float(h2), v3 - __bfloat162float(h3));
    }
}

// ---------------------------------------------------------------------------
extern "C" void kernel_launch(void* const* d_in, const int* in_sizes, int n_in,
                              void* d_out, int out_size)
{
    const float* x     = (const float*)d_in[0];
    const float* w_qkv = (const float*)d_in[1];
    const float* b_qkv = (const float*)d_in[2];
    const float* w_out = (const float*)d_in[3];
    const float* b_out = (const float*)d_in[4];
    float* out = (float*)d_out;

    bf16 *xhi, *xlo, *qh, *ql, *ahi, *alo, *wqh, *wql, *woh, *wol;
    cudaGetSymbolAddress((void**)&xhi, g_xhi);
    cudaGetSymbolAddress((void**)&xlo, g_xlo);
    cudaGetSymbolAddress((void**)&qh,  g_qkvhi);
    cudaGetSymbolAddress((void**)&ql,  g_qkvlo);
    cudaGetSymbolAddress((void**)&ahi, g_ahi);
    cudaGetSymbolAddress((void**)&alo, g_alo);
    cudaGetSymbolAddress((void**)&wqh, g_wqt_hi);
    cudaGetSymbolAddress((void**)&wql, g_wqt_lo);
    cudaGetSymbolAddress((void**)&woh, g_wot_hi);
    cudaGetSymbolAddress((void**)&wol, g_wot_lo);

    cudaFuncSetAttribute(attn_tc_kernel,
                         cudaFuncAttributeMaxDynamicSharedMemorySize,
                         ATTN_SMEM_BYTES);
    cudaFuncSetAttribute(gemm_tc_kernel<true>,
                         cudaFuncAttributeMaxDynamicSharedMemorySize,
                         GEMM_SMEM_BYTES);
    cudaFuncSetAttribute(gemm_tc_kernel<false>,
                         cudaFuncAttributeMaxDynamicSharedMemorySize,
                         GEMM_SMEM_BYTES);

    // 0a) split x -> bf16 hi/lo
    {
        int n4 = (MROWS * DM) / 4;
        split_kernel<<<n4 / 256, 256>>>((const float4*)x,
                                        (__nv_bfloat162*)xhi, (__nv_bfloat162*)xlo, n4);
    }
    // 0b) transpose+split weights
    {
        dim3 b32(32, 8);
        dim3 gq(QKV_N / 32, DM / 32);
        transpose_split_kernel<<<gq, b32>>>(w_qkv, wqh, wql, DM, QKV_N);
        dim3 go(DM / 32, DM / 32);
        transpose_split_kernel<<<go, b32>>>(w_out, woh, wol, DM, DM);
    }
    // 1) QKV projection -> split bf16 output
    {
        dim3 g1(QKV_N / 128, MROWS / 128);
        gemm_tc_kernel<true><<<g1, 256, GEMM_SMEM_BYTES>>>(
            xhi, xlo, wqh, wql, b_qkv, nullptr, qh, ql, MROWS, QKV_N, DM);
    }
    // 2) Attention (all-bf16 dataflow) -> split bf16 output
    {
        dim3 g2(SEQ / QTILE, NH, BATCH);
        attn_tc_kernel<<<g2, 256, ATTN_SMEM_BYTES>>>(qh, ql, ahi, alo);
    }
    // 3) Output projection -> fp32
    {
        dim3 g3(DM / 128, MROWS / 128);
        gemm_tc_kernel<false><<<g3, 256, GEMM_SMEM_BYTES>>>(
            ahi, alo, woh, wol, b_out, out, nullptr, nullptr, MROWS, DM, DM);
    }
}